// round 1
// baseline (speedup 1.0000x reference)
#include <cuda_runtime.h>
#include <math.h>

#define BB 8
#define TT 2048
#define CC 384
#define HH 64
#define NTOK (BB * TT)   // 16384

// Scratch (allocation-free rule: __device__ globals)
__device__ float g_qkv[3 * NTOK * HH];            // q | k | v, each (B,T,H)
__device__ float g_S[(size_t)BB * TT * TT];       // scores, 128 MB
__device__ float g_m[NTOK];                       // per-(b,s) column max
__device__ float g_rZ[NTOK];                      // per-(b,s) 1/Z

// ---------------------------------------------------------------------------
// Kernel A: fused QKV projection. grid(NTOK/64, 3), 256 thr.
// out[w] (64 rows x 64 cols) = X(64x384) @ W[w](384x64)
// ---------------------------------------------------------------------------
__global__ void qkv_kernel(const float* __restrict__ x,
                           const float* __restrict__ Wq,
                           const float* __restrict__ Wk,
                           const float* __restrict__ Wv) {
    __shared__ float Xs[64][65];
    __shared__ float Ws[64][65];
    const float* W = (blockIdx.y == 0) ? Wq : ((blockIdx.y == 1) ? Wk : Wv);
    const int r0  = blockIdx.x * 64;
    const int tid = threadIdx.x;
    const int tx  = tid & 15;      // 16 col groups
    const int ty  = tid >> 4;      // 16 row groups
    float acc[4][4] = {};

    for (int k0 = 0; k0 < CC; k0 += 64) {
        for (int i = tid; i < 64 * 64; i += 256) {
            int r = i >> 6, c = i & 63;
            Xs[r][c] = x[(size_t)(r0 + r) * CC + (k0 + c)];
            Ws[r][c] = W[(k0 + r) * HH + c];
        }
        __syncthreads();
        #pragma unroll
        for (int kk = 0; kk < 64; kk++) {
            float a[4], b[4];
            #pragma unroll
            for (int i = 0; i < 4; i++) a[i] = Xs[ty * 4 + i][kk];
            #pragma unroll
            for (int j = 0; j < 4; j++) b[j] = Ws[kk][tx * 4 + j];
            #pragma unroll
            for (int i = 0; i < 4; i++)
                #pragma unroll
                for (int j = 0; j < 4; j++)
                    acc[i][j] += a[i] * b[j];
        }
        __syncthreads();
    }

    float* dst = &g_qkv[(size_t)blockIdx.y * NTOK * HH];
    #pragma unroll
    for (int i = 0; i < 4; i++)
        #pragma unroll
        for (int j = 0; j < 4; j++)
            dst[(size_t)(r0 + ty * 4 + i) * HH + tx * 4 + j] = acc[i][j];
}

// ---------------------------------------------------------------------------
// Kernel B: S[b,t,s] = scale * q[b,t].k[b,s], causal (-inf above diag).
// grid(T/64 s-tiles, T/64 t-tiles, B), 256 thr. Skip tiles fully above diag.
// ---------------------------------------------------------------------------
__global__ void score_kernel() {
    const int si = blockIdx.x, ti = blockIdx.y, b = blockIdx.z;
    if (ti < si) return;                       // fully masked tile
    const int t0 = ti * 64, s0 = si * 64;

    __shared__ float Qs[64][65];
    __shared__ float KsT[64][65];              // [h][s]

    const float* q = &g_qkv[(size_t)b * TT * HH];
    const float* k = &g_qkv[(size_t)(NTOK + b * TT) * HH];
    const int tid = threadIdx.x;

    for (int i = tid; i < 64 * 64; i += 256) {
        int r = i >> 6, c = i & 63;            // c = h
        Qs[r][c]  = q[(size_t)(t0 + r) * HH + c];
        KsT[c][r] = k[(size_t)(s0 + r) * HH + c];
    }
    __syncthreads();

    const int tx = tid & 15, ty = tid >> 4;
    float acc[4][4] = {};
    #pragma unroll
    for (int h = 0; h < 64; h++) {
        float a[4], bb[4];
        #pragma unroll
        for (int i = 0; i < 4; i++) a[i] = Qs[ty * 4 + i][h];
        #pragma unroll
        for (int j = 0; j < 4; j++) bb[j] = KsT[h][tx * 4 + j];
        #pragma unroll
        for (int i = 0; i < 4; i++)
            #pragma unroll
            for (int j = 0; j < 4; j++)
                acc[i][j] += a[i] * bb[j];
    }

    const float scale = rsqrtf((float)CC);
    float* Sb = &g_S[(size_t)b * TT * TT];
    #pragma unroll
    for (int i = 0; i < 4; i++) {
        int t = t0 + ty * 4 + i;
        #pragma unroll
        for (int j = 0; j < 4; j++) {
            int s = s0 + tx * 4 + j;
            Sb[(size_t)t * TT + s] = (s <= t) ? acc[i][j] * scale : -INFINITY;
        }
    }
}

// ---------------------------------------------------------------------------
// Kernel C: column-wise online softmax stats over t >= s.
// grid(T/32, B), 256 thr = 8(t-lanes) x 32(s).
// ---------------------------------------------------------------------------
__global__ void colstats_kernel() {
    const int b  = blockIdx.y;
    const int s0 = blockIdx.x * 32;
    const int tx = threadIdx.x & 31;
    const int ty = threadIdx.x >> 5;
    const int s  = s0 + tx;
    const int t_start = (s0 / 64) * 64;        // first written tile row
    const float* Sb = &g_S[(size_t)b * TT * TT];

    float m = -INFINITY, z = 0.f;
    for (int t = t_start + ty; t < TT; t += 8) {
        float v = Sb[(size_t)t * TT + s];
        if (v != -INFINITY) {
            if (v > m) { z = z * __expf(m - v) + 1.f; m = v; }
            else       { z += __expf(v - m); }
        }
    }

    __shared__ float sm[8][32], sz[8][32];
    sm[ty][tx] = m; sz[ty][tx] = z;
    __syncthreads();

    if (ty == 0) {
        float M = m, Z = z;
        #pragma unroll
        for (int j = 1; j < 8; j++) {
            float mj = sm[j][tx], zj = sz[j][tx];
            if (zj == 0.f) continue;
            if (mj > M) { Z = Z * __expf(M - mj) + zj; M = mj; }
            else        { Z += zj * __expf(mj - M); }
        }
        g_m[b * TT + s]  = M;
        g_rZ[b * TT + s] = 1.f / Z;
    }
}

// ---------------------------------------------------------------------------
// Kernel D: O[b,t,:] = sum_{s<=t} exp(S[t,s]-m[s])/Z[s] * v[b,s,:]
// grid(T/64 t-tiles, B), 256 thr.
// ---------------------------------------------------------------------------
__global__ void pv_kernel(float* __restrict__ out) {
    const int b  = blockIdx.y;
    const int t0 = blockIdx.x * 64;
    const int tid = threadIdx.x;
    const int tx = tid & 15, ty = tid >> 4;

    __shared__ float Ps[64][65];
    __shared__ float Vs[64][65];

    const float* Sb   = &g_S[(size_t)b * TT * TT];
    const float* v    = &g_qkv[(size_t)(2 * NTOK + b * TT) * HH];
    const float* mcol = &g_m[b * TT];
    const float* rz   = &g_rZ[b * TT];

    float acc[4][4] = {};
    const int nTiles = blockIdx.x + 1;         // lower-triangular range

    for (int st = 0; st < nTiles; st++) {
        const int s0 = st * 64;
        for (int i = tid; i < 64 * 64; i += 256) {
            int r = i >> 6, c = i & 63;
            float val = Sb[(size_t)(t0 + r) * TT + (s0 + c)];
            Ps[r][c] = (val == -INFINITY)
                       ? 0.f
                       : __expf(val - mcol[s0 + c]) * rz[s0 + c];
            Vs[r][c] = v[(size_t)(s0 + r) * HH + c];
        }
        __syncthreads();
        #pragma unroll
        for (int kk = 0; kk < 64; kk++) {
            float a[4], bb[4];
            #pragma unroll
            for (int i = 0; i < 4; i++) a[i] = Ps[ty * 4 + i][kk];
            #pragma unroll
            for (int j = 0; j < 4; j++) bb[j] = Vs[kk][tx * 4 + j];
            #pragma unroll
            for (int i = 0; i < 4; i++)
                #pragma unroll
                for (int j = 0; j < 4; j++)
                    acc[i][j] += a[i] * bb[j];
        }
        __syncthreads();
    }

    #pragma unroll
    for (int i = 0; i < 4; i++)
        #pragma unroll
        for (int j = 0; j < 4; j++)
            out[(size_t)(b * TT + t0 + ty * 4 + i) * HH + tx * 4 + j] = acc[i][j];
}

// ---------------------------------------------------------------------------
extern "C" void kernel_launch(void* const* d_in, const int* in_sizes, int n_in,
                              void* d_out, int out_size) {
    const float* x  = (const float*)d_in[0];
    const float* Wq = (const float*)d_in[1];
    const float* Wk = (const float*)d_in[2];
    const float* Wv = (const float*)d_in[3];
    float* out = (float*)d_out;

    qkv_kernel<<<dim3(NTOK / 64, 3), 256>>>(x, Wq, Wk, Wv);
    score_kernel<<<dim3(TT / 64, TT / 64, BB), 256>>>();
    colstats_kernel<<<dim3(TT / 32, BB), 256>>>();
    pv_kernel<<<dim3(TT / 64, BB), 256>>>(out);
}

// round 2
// speedup vs baseline: 2.2963x; 2.2963x over previous
#include <cuda_runtime.h>
#include <math.h>
#include <stdint.h>

#define BB 8
#define TT 2048
#define CC 384
#define HH 64
#define NTOK (BB * TT)   // 16384

// Scratch (allocation-free rule: __device__ globals)
__device__ float g_qkv[3 * NTOK * HH];            // q | k | v (fp32)
__device__ float g_S[(size_t)BB * TT * TT];       // scores, 128 MB
__device__ float g_m[NTOK];                       // per-(b,s) column max
__device__ float g_rZ[NTOK];                      // per-(b,s) 1/Z

__device__ __forceinline__ uint32_t f2tf(float f) {
    uint32_t r; asm("cvt.rna.tf32.f32 %0, %1;" : "=r"(r) : "f"(f)); return r;
}

__device__ __forceinline__ void mma8(float* c, const uint32_t* a, const uint32_t* b) {
    asm volatile(
        "mma.sync.aligned.m16n8k8.row.col.f32.tf32.tf32.f32 "
        "{%0,%1,%2,%3}, {%4,%5,%6,%7}, {%8,%9}, {%0,%1,%2,%3};\n"
        : "+f"(c[0]), "+f"(c[1]), "+f"(c[2]), "+f"(c[3])
        : "r"(a[0]), "r"(a[1]), "r"(a[2]), "r"(a[3]), "r"(b[0]), "r"(b[1]));
}

// ---------------------------------------------------------------------------
// Kernel A: fused QKV projection, tf32 mma. grid(NTOK/128, 3), 256 thr.
// out[w] (128 x 64) = X(128x384) @ W[w](384x64)
// Warps 4(m) x 2(n): warp tile 32x32.
// ---------------------------------------------------------------------------
__global__ void qkv_kernel(const float* __restrict__ x,
                           const float* __restrict__ Wq,
                           const float* __restrict__ Wk,
                           const float* __restrict__ Wv) {
    __shared__ uint32_t Xs[128][36];   // pad 36 (==4 mod 32): A-pattern conflict-free
    __shared__ uint32_t Ws[32][72];    // pad 72 (==8 mod 32): B-pattern conflict-free
    const float* W = (blockIdx.y == 0) ? Wq : ((blockIdx.y == 1) ? Wk : Wv);
    const int r0  = blockIdx.x * 128;
    const int tid = threadIdx.x, lane = tid & 31, wid = tid >> 5;
    const int lr = lane >> 2, lc = lane & 3;
    const int wm = (wid >> 1) * 32, wn = (wid & 1) * 32;
    float acc[2][4][4] = {};

    for (int k0 = 0; k0 < CC; k0 += 32) {
        for (int i = tid; i < 1024; i += 256) {          // X tile 128x32
            int r = i >> 3, c4 = i & 7;
            float4 v = *(const float4*)&x[(size_t)(r0 + r) * CC + k0 + c4 * 4];
            *(uint4*)&Xs[r][c4 * 4] = make_uint4(f2tf(v.x), f2tf(v.y), f2tf(v.z), f2tf(v.w));
        }
        for (int i = tid; i < 512; i += 256) {           // W tile 32x64
            int r = i >> 4, c4 = i & 15;
            float4 v = *(const float4*)&W[(k0 + r) * HH + c4 * 4];
            *(uint4*)&Ws[r][c4 * 4] = make_uint4(f2tf(v.x), f2tf(v.y), f2tf(v.z), f2tf(v.w));
        }
        __syncthreads();
        #pragma unroll
        for (int ks = 0; ks < 4; ks++) {
            const int k = ks * 8;
            uint32_t a[2][4], bf[4][2];
            #pragma unroll
            for (int mi = 0; mi < 2; mi++) {
                int rb = wm + mi * 16;
                a[mi][0] = Xs[rb + lr][k + lc];
                a[mi][1] = Xs[rb + lr + 8][k + lc];
                a[mi][2] = Xs[rb + lr][k + lc + 4];
                a[mi][3] = Xs[rb + lr + 8][k + lc + 4];
            }
            #pragma unroll
            for (int ni = 0; ni < 4; ni++) {
                int cb = wn + ni * 8 + lr;
                bf[ni][0] = Ws[k + lc][cb];
                bf[ni][1] = Ws[k + lc + 4][cb];
            }
            #pragma unroll
            for (int mi = 0; mi < 2; mi++)
                #pragma unroll
                for (int ni = 0; ni < 4; ni++)
                    mma8(acc[mi][ni], a[mi], bf[ni]);
        }
        __syncthreads();
    }

    float* dst = &g_qkv[(size_t)blockIdx.y * NTOK * HH];
    #pragma unroll
    for (int mi = 0; mi < 2; mi++)
        #pragma unroll
        for (int ni = 0; ni < 4; ni++) {
            int row = r0 + wm + mi * 16 + lr;
            int col = wn + ni * 8 + 2 * lc;
            *(float2*)&dst[(size_t)row * HH + col] =
                make_float2(acc[mi][ni][0], acc[mi][ni][1]);
            *(float2*)&dst[(size_t)(row + 8) * HH + col] =
                make_float2(acc[mi][ni][2], acc[mi][ni][3]);
        }
}

// ---------------------------------------------------------------------------
// Kernel B: S = scale * Q K^T with causal mask, tf32 mma, 128x128 tiles.
// grid(16 s-tiles, 16 t-tiles, B), 256 thr. Warps 2(m) x 4(n): 64x32 each.
// ---------------------------------------------------------------------------
__global__ void score_kernel() {
    extern __shared__ uint32_t sm_[];
    uint32_t (*Qs)[68] = (uint32_t(*)[68])sm_;              // pad 68 (==4 mod 32)
    uint32_t (*Ks)[68] = (uint32_t(*)[68])(sm_ + 128 * 68);
    const int si = blockIdx.x, ti = blockIdx.y, b = blockIdx.z;
    if (ti < si) return;
    const int t0 = ti * 128, s0 = si * 128;
    const float* q  = &g_qkv[(size_t)b * TT * HH];
    const float* kp = &g_qkv[(size_t)(NTOK + b * TT) * HH];
    const int tid = threadIdx.x, lane = tid & 31, wid = tid >> 5;
    const int lr = lane >> 2, lc = lane & 3;
    const int wm = (wid >> 2) * 64, wn = (wid & 3) * 32;

    for (int i = tid; i < 2048; i += 256) {                 // 128x64 each
        int r = i >> 4, c4 = i & 15;
        float4 v = *(const float4*)&q[(size_t)(t0 + r) * HH + c4 * 4];
        *(uint4*)&Qs[r][c4 * 4] = make_uint4(f2tf(v.x), f2tf(v.y), f2tf(v.z), f2tf(v.w));
        float4 w = *(const float4*)&kp[(size_t)(s0 + r) * HH + c4 * 4];
        *(uint4*)&Ks[r][c4 * 4] = make_uint4(f2tf(w.x), f2tf(w.y), f2tf(w.z), f2tf(w.w));
    }
    __syncthreads();

    float acc[4][4][4] = {};
    #pragma unroll
    for (int ks = 0; ks < 8; ks++) {
        const int k = ks * 8;
        uint32_t a[4][4], bf[4][2];
        #pragma unroll
        for (int mi = 0; mi < 4; mi++) {
            int rb = wm + mi * 16;
            a[mi][0] = Qs[rb + lr][k + lc];
            a[mi][1] = Qs[rb + lr + 8][k + lc];
            a[mi][2] = Qs[rb + lr][k + lc + 4];
            a[mi][3] = Qs[rb + lr + 8][k + lc + 4];
        }
        #pragma unroll
        for (int ni = 0; ni < 4; ni++) {
            int sb = wn + ni * 8 + lr;
            bf[ni][0] = Ks[sb][k + lc];
            bf[ni][1] = Ks[sb][k + lc + 4];
        }
        #pragma unroll
        for (int mi = 0; mi < 4; mi++)
            #pragma unroll
            for (int ni = 0; ni < 4; ni++)
                mma8(acc[mi][ni], a[mi], bf[ni]);
    }

    const float scale = rsqrtf((float)CC);
    float* Sb = &g_S[(size_t)b * TT * TT];
    #pragma unroll
    for (int mi = 0; mi < 4; mi++)
        #pragma unroll
        for (int ni = 0; ni < 4; ni++) {
            int tg = t0 + wm + mi * 16 + lr;
            int sg = s0 + wn + ni * 8 + 2 * lc;
            float2 v;
            v.x = (sg     <= tg) ? acc[mi][ni][0] * scale : -INFINITY;
            v.y = (sg + 1 <= tg) ? acc[mi][ni][1] * scale : -INFINITY;
            *(float2*)&Sb[(size_t)tg * TT + sg] = v;
            int tg2 = tg + 8;
            v.x = (sg     <= tg2) ? acc[mi][ni][2] * scale : -INFINITY;
            v.y = (sg + 1 <= tg2) ? acc[mi][ni][3] * scale : -INFINITY;
            *(float2*)&Sb[(size_t)tg2 * TT + sg] = v;
        }
}

// ---------------------------------------------------------------------------
// Kernel C: column-wise softmax stats over t >= s. grid(T/32, B), 256 thr.
// ---------------------------------------------------------------------------
__global__ void colstats_kernel() {
    const int b  = blockIdx.y;
    const int s0 = blockIdx.x * 32;
    const int tx = threadIdx.x & 31;
    const int ty = threadIdx.x >> 5;
    const int s  = s0 + tx;
    const int t_start = (s0 / 128) * 128;      // 128-tile granularity now
    const float* Sb = &g_S[(size_t)b * TT * TT];

    float m = -INFINITY, z = 0.f;
    for (int t = t_start + ty; t < TT; t += 8) {
        float v = Sb[(size_t)t * TT + s];
        if (v != -INFINITY) {
            if (v > m) { z = z * __expf(m - v) + 1.f; m = v; }
            else       { z += __expf(v - m); }
        }
    }

    __shared__ float sm[8][32], sz[8][32];
    sm[ty][tx] = m; sz[ty][tx] = z;
    __syncthreads();

    if (ty == 0) {
        float M = m, Z = z;
        #pragma unroll
        for (int j = 1; j < 8; j++) {
            float mj = sm[j][tx], zj = sz[j][tx];
            if (zj == 0.f) continue;
            if (mj > M) { Z = Z * __expf(M - mj) + zj; M = mj; }
            else        { Z += zj * __expf(mj - M); }
        }
        g_m[b * TT + s]  = M;
        g_rZ[b * TT + s] = 1.f / Z;
    }
}

// ---------------------------------------------------------------------------
// Kernel D: O += P V over an s-chunk (up to 4 s-tiles of 128), tf32 mma.
// grid(4 chunks, 16 t-tiles, B), 256 thr. Warps 4(m) x 2(n): 32x32 each.
// Epilogue: fp32 atomicAdd into zero-initialized out.
// ---------------------------------------------------------------------------
__global__ void pv_kernel(float* __restrict__ out) {
    extern __shared__ uint32_t sm_[];
    uint32_t (*Ps)[132] = (uint32_t(*)[132])sm_;             // pad 132 (==4 mod 32)
    uint32_t (*Vs)[72]  = (uint32_t(*)[72])(sm_ + 128 * 132); // pad 72 (==8 mod 32)
    const int chunk = blockIdx.x, ti = blockIdx.y, b = blockIdx.z;
    const int sBeg = chunk * 4;
    if (sBeg > ti) return;
    const int sEnd = min(sBeg + 4, ti + 1);
    const int t0 = ti * 128;
    const float* Sb   = &g_S[(size_t)b * TT * TT];
    const float* vp   = &g_qkv[(size_t)(2 * NTOK + b * TT) * HH];
    const float* mcol = &g_m[b * TT];
    const float* rz   = &g_rZ[b * TT];
    const int tid = threadIdx.x, lane = tid & 31, wid = tid >> 5;
    const int lr = lane >> 2, lc = lane & 3;
    const int wm = (wid >> 1) * 32, wn = (wid & 1) * 32;

    float acc[2][4][4] = {};

    for (int si = sBeg; si < sEnd; si++) {
        const int s0 = si * 128;
        for (int i = tid; i < 4096; i += 256) {              // P tile 128x128
            int r = i >> 5, c4 = i & 31;
            float4 v  = *(const float4*)&Sb[(size_t)(t0 + r) * TT + s0 + c4 * 4];
            float4 mm = *(const float4*)&mcol[s0 + c4 * 4];
            float4 zz = *(const float4*)&rz[s0 + c4 * 4];
            uint4 u;
            u.x = f2tf(v.x == -INFINITY ? 0.f : __expf(v.x - mm.x) * zz.x);
            u.y = f2tf(v.y == -INFINITY ? 0.f : __expf(v.y - mm.y) * zz.y);
            u.z = f2tf(v.z == -INFINITY ? 0.f : __expf(v.z - mm.z) * zz.z);
            u.w = f2tf(v.w == -INFINITY ? 0.f : __expf(v.w - mm.w) * zz.w);
            *(uint4*)&Ps[r][c4 * 4] = u;
        }
        for (int i = tid; i < 2048; i += 256) {              // V tile 128x64
            int r = i >> 4, c4 = i & 15;
            float4 v = *(const float4*)&vp[(size_t)(s0 + r) * HH + c4 * 4];
            *(uint4*)&Vs[r][c4 * 4] = make_uint4(f2tf(v.x), f2tf(v.y), f2tf(v.z), f2tf(v.w));
        }
        __syncthreads();
        #pragma unroll
        for (int ks = 0; ks < 16; ks++) {
            const int k = ks * 8;
            uint32_t a[2][4], bf[4][2];
            #pragma unroll
            for (int mi = 0; mi < 2; mi++) {
                int rb = wm + mi * 16;
                a[mi][0] = Ps[rb + lr][k + lc];
                a[mi][1] = Ps[rb + lr + 8][k + lc];
                a[mi][2] = Ps[rb + lr][k + lc + 4];
                a[mi][3] = Ps[rb + lr + 8][k + lc + 4];
            }
            #pragma unroll
            for (int ni = 0; ni < 4; ni++) {
                int cb = wn + ni * 8 + lr;
                bf[ni][0] = Vs[k + lc][cb];
                bf[ni][1] = Vs[k + lc + 4][cb];
            }
            #pragma unroll
            for (int mi = 0; mi < 2; mi++)
                #pragma unroll
                for (int ni = 0; ni < 4; ni++)
                    mma8(acc[mi][ni], a[mi], bf[ni]);
        }
        __syncthreads();
    }

    #pragma unroll
    for (int mi = 0; mi < 2; mi++)
        #pragma unroll
        for (int ni = 0; ni < 4; ni++) {
            int row = b * TT + t0 + wm + mi * 16 + lr;
            int col = wn + ni * 8 + 2 * lc;
            float* o = &out[(size_t)row * HH + col];
            atomicAdd(o,     acc[mi][ni][0]);
            atomicAdd(o + 1, acc[mi][ni][1]);
            float* o2 = o + 8 * HH;
            atomicAdd(o2,     acc[mi][ni][2]);
            atomicAdd(o2 + 1, acc[mi][ni][3]);
        }
}

// ---------------------------------------------------------------------------
extern "C" void kernel_launch(void* const* d_in, const int* in_sizes, int n_in,
                              void* d_out, int out_size) {
    const float* x  = (const float*)d_in[0];
    const float* Wq = (const float*)d_in[1];
    const float* Wk = (const float*)d_in[2];
    const float* Wv = (const float*)d_in[3];
    float* out = (float*)d_out;

    const int score_smem = 2 * 128 * 68 * 4;                 // 69632
    const int pv_smem    = (128 * 132 + 128 * 72) * 4;       // 104448
    cudaFuncSetAttribute(score_kernel, cudaFuncAttributeMaxDynamicSharedMemorySize, score_smem);
    cudaFuncSetAttribute(pv_kernel,    cudaFuncAttributeMaxDynamicSharedMemorySize, pv_smem);

    cudaMemsetAsync(d_out, 0, (size_t)out_size * sizeof(float));
    qkv_kernel<<<dim3(NTOK / 128, 3), 256>>>(x, Wq, Wk, Wv);
    score_kernel<<<dim3(16, 16, BB), 256, score_smem>>>();
    colstats_kernel<<<dim3(TT / 32, BB), 256>>>();
    pv_kernel<<<dim3(4, 16, BB), 256, pv_smem>>>(out);
}

// round 3
// speedup vs baseline: 2.6766x; 1.1656x over previous
#include <cuda_runtime.h>
#include <math.h>
#include <stdint.h>

#define BB 8
#define TT 2048
#define CC 384
#define HH 64
#define NTOK (BB * TT)   // 16384

__device__ float g_qkv[3 * NTOK * HH];            // q | k | v (fp32)
__device__ float g_Z[NTOK];                       // per-(b,s) column sum of exp
__device__ float g_rZ[NTOK];                      // 1/Z

__device__ __forceinline__ uint32_t f2tf(float f) {
    uint32_t r; asm("cvt.rna.tf32.f32 %0, %1;" : "=r"(r) : "f"(f)); return r;
}

__device__ __forceinline__ void mma8(float* c, const uint32_t* a, const uint32_t* b) {
    asm volatile(
        "mma.sync.aligned.m16n8k8.row.col.f32.tf32.tf32.f32 "
        "{%0,%1,%2,%3}, {%4,%5,%6,%7}, {%8,%9}, {%0,%1,%2,%3};\n"
        : "+f"(c[0]), "+f"(c[1]), "+f"(c[2]), "+f"(c[3])
        : "r"(a[0]), "r"(a[1]), "r"(a[2]), "r"(a[3]), "r"(b[0]), "r"(b[1]));
}

// ---------------------------------------------------------------------------
// Kernel A: fused QKV projection, tf32 mma. grid(NTOK/128, 3), 256 thr.
// ---------------------------------------------------------------------------
__global__ void qkv_kernel(const float* __restrict__ x,
                           const float* __restrict__ Wq,
                           const float* __restrict__ Wk,
                           const float* __restrict__ Wv) {
    __shared__ uint32_t Xs[128][36];   // pad ==4 mod 32: A-pattern conflict-free
    __shared__ uint32_t Ws[32][72];    // pad ==8 mod 32: B-pattern conflict-free
    const float* W = (blockIdx.y == 0) ? Wq : ((blockIdx.y == 1) ? Wk : Wv);
    const int r0  = blockIdx.x * 128;
    const int tid = threadIdx.x, lane = tid & 31, wid = tid >> 5;
    const int lr = lane >> 2, lc = lane & 3;
    const int wm = (wid >> 1) * 32, wn = (wid & 1) * 32;
    float acc[2][4][4] = {};

    for (int k0 = 0; k0 < CC; k0 += 32) {
        for (int i = tid; i < 1024; i += 256) {
            int r = i >> 3, c4 = i & 7;
            float4 v = *(const float4*)&x[(size_t)(r0 + r) * CC + k0 + c4 * 4];
            *(uint4*)&Xs[r][c4 * 4] = make_uint4(f2tf(v.x), f2tf(v.y), f2tf(v.z), f2tf(v.w));
        }
        for (int i = tid; i < 512; i += 256) {
            int r = i >> 4, c4 = i & 15;
            float4 v = *(const float4*)&W[(k0 + r) * HH + c4 * 4];
            *(uint4*)&Ws[r][c4 * 4] = make_uint4(f2tf(v.x), f2tf(v.y), f2tf(v.z), f2tf(v.w));
        }
        __syncthreads();
        #pragma unroll
        for (int ks = 0; ks < 4; ks++) {
            const int k = ks * 8;
            uint32_t a[2][4], bf[4][2];
            #pragma unroll
            for (int mi = 0; mi < 2; mi++) {
                int rb = wm + mi * 16;
                a[mi][0] = Xs[rb + lr][k + lc];
                a[mi][1] = Xs[rb + lr + 8][k + lc];
                a[mi][2] = Xs[rb + lr][k + lc + 4];
                a[mi][3] = Xs[rb + lr + 8][k + lc + 4];
            }
            #pragma unroll
            for (int ni = 0; ni < 4; ni++) {
                int cb = wn + ni * 8 + lr;
                bf[ni][0] = Ws[k + lc][cb];
                bf[ni][1] = Ws[k + lc + 4][cb];
            }
            #pragma unroll
            for (int mi = 0; mi < 2; mi++)
                #pragma unroll
                for (int ni = 0; ni < 4; ni++)
                    mma8(acc[mi][ni], a[mi], bf[ni]);
        }
        __syncthreads();
    }

    float* dst = &g_qkv[(size_t)blockIdx.y * NTOK * HH];
    #pragma unroll
    for (int mi = 0; mi < 2; mi++)
        #pragma unroll
        for (int ni = 0; ni < 4; ni++) {
            int row = r0 + wm + mi * 16 + lr;
            int col = wn + ni * 8 + 2 * lc;
            *(float2*)&dst[(size_t)row * HH + col] =
                make_float2(acc[mi][ni][0], acc[mi][ni][1]);
            *(float2*)&dst[(size_t)(row + 8) * HH + col] =
                make_float2(acc[mi][ni][2], acc[mi][ni][3]);
        }
}

__global__ void zeroZ_kernel() {
    g_Z[blockIdx.x * 256 + threadIdx.x] = 0.f;
}

__global__ void recip_kernel() {
    int i = blockIdx.x * 256 + threadIdx.x;
    g_rZ[i] = 1.f / g_Z[i];
}

// ---------------------------------------------------------------------------
// Kernel B: column sums Z[s] = sum_{t>=s} exp(scale*q_t.k_s). No S storage.
// grid(16 s-tiles, 2 t-chunks, B), 256 thr. K tile persistent; loop Q tiles.
// Warp layout 2(m)x4(n), warp tile 64x32 of the 128x128 S tile.
// ---------------------------------------------------------------------------
__global__ void __launch_bounds__(256, 2) stats_kernel() {
    extern __shared__ uint32_t sm_[];
    uint32_t (*Qs)[68] = (uint32_t(*)[68])sm_;              // pad ==4 mod 32
    uint32_t (*Ks)[68] = (uint32_t(*)[68])(sm_ + 128 * 68);
    const int si = blockIdx.x, c = blockIdx.y, b = blockIdx.z;
    const int tBeg = max(si, c * 8), tEnd = min(16, c * 8 + 8);
    if (tBeg >= tEnd) return;
    const int s0 = si * 128;
    const float* q  = &g_qkv[(size_t)b * TT * HH];
    const float* kp = &g_qkv[(size_t)(NTOK + b * TT) * HH];
    const int tid = threadIdx.x, lane = tid & 31, wid = tid >> 5;
    const int lr = lane >> 2, lc = lane & 3;
    const int wm = (wid >> 2) * 64, wn = (wid & 3) * 32;
    const float scale = rsqrtf((float)CC);

    for (int i = tid; i < 2048; i += 256) {                 // K tile 128x64
        int r = i >> 4, c4 = i & 15;
        float4 w = *(const float4*)&kp[(size_t)(s0 + r) * HH + c4 * 4];
        *(uint4*)&Ks[r][c4 * 4] = make_uint4(f2tf(w.x), f2tf(w.y), f2tf(w.z), f2tf(w.w));
    }

    float colsum[4][2] = {};
    for (int ti = tBeg; ti < tEnd; ti++) {
        const int t0 = ti * 128;
        for (int i = tid; i < 2048; i += 256) {             // Q tile 128x64
            int r = i >> 4, c4 = i & 15;
            float4 v = *(const float4*)&q[(size_t)(t0 + r) * HH + c4 * 4];
            *(uint4*)&Qs[r][c4 * 4] = make_uint4(f2tf(v.x), f2tf(v.y), f2tf(v.z), f2tf(v.w));
        }
        __syncthreads();

        float acc[4][4][4] = {};
        #pragma unroll
        for (int ks = 0; ks < 8; ks++) {
            const int k = ks * 8;
            uint32_t a[4][4], bf[4][2];
            #pragma unroll
            for (int mi = 0; mi < 4; mi++) {
                int rb = wm + mi * 16;
                a[mi][0] = Qs[rb + lr][k + lc];
                a[mi][1] = Qs[rb + lr + 8][k + lc];
                a[mi][2] = Qs[rb + lr][k + lc + 4];
                a[mi][3] = Qs[rb + lr + 8][k + lc + 4];
            }
            #pragma unroll
            for (int ni = 0; ni < 4; ni++) {
                int sb = wn + ni * 8 + lr;
                bf[ni][0] = Ks[sb][k + lc];
                bf[ni][1] = Ks[sb][k + lc + 4];
            }
            #pragma unroll
            for (int mi = 0; mi < 4; mi++)
                #pragma unroll
                for (int ni = 0; ni < 4; ni++)
                    mma8(acc[mi][ni], a[mi], bf[ni]);
        }

        #pragma unroll
        for (int mi = 0; mi < 4; mi++)
            #pragma unroll
            for (int ni = 0; ni < 4; ni++) {
                int tg = t0 + wm + mi * 16 + lr;
                int sg = s0 + wn + ni * 8 + 2 * lc;
                float e0 = (tg >= sg)         ? __expf(acc[mi][ni][0] * scale) : 0.f;
                float e1 = (tg >= sg + 1)     ? __expf(acc[mi][ni][1] * scale) : 0.f;
                float e2 = (tg + 8 >= sg)     ? __expf(acc[mi][ni][2] * scale) : 0.f;
                float e3 = (tg + 8 >= sg + 1) ? __expf(acc[mi][ni][3] * scale) : 0.f;
                colsum[ni][0] += e0 + e2;
                colsum[ni][1] += e1 + e3;
            }
        __syncthreads();
    }

    // reduce over lr (lane bits 2..4), then atomicAdd per column
    #pragma unroll
    for (int ni = 0; ni < 4; ni++)
        #pragma unroll
        for (int jj = 0; jj < 2; jj++) {
            float v = colsum[ni][jj];
            v += __shfl_xor_sync(0xffffffffu, v, 16);
            v += __shfl_xor_sync(0xffffffffu, v, 8);
            v += __shfl_xor_sync(0xffffffffu, v, 4);
            colsum[ni][jj] = v;
        }
    if (lr == 0) {
        #pragma unroll
        for (int ni = 0; ni < 4; ni++) {
            int sg = s0 + wn + ni * 8 + 2 * lc;
            atomicAdd(&g_Z[b * TT + sg],     colsum[ni][0]);
            atomicAdd(&g_Z[b * TT + sg + 1], colsum[ni][1]);
        }
    }
}

// ---------------------------------------------------------------------------
// Kernel D: fused recompute + PV. Per block: t-tile 128, s-chunk of up to
// eight 64-wide s-tiles. O accumulated in regs, atomicAdd epilogue.
// grid(4 s-chunks, 16 t-tiles, B), 256 thr.
// ---------------------------------------------------------------------------
__global__ void __launch_bounds__(256, 2) pv_kernel(float* __restrict__ out) {
    extern __shared__ uint32_t sm_[];
    uint32_t (*Qs)[68] = (uint32_t(*)[68])sm_;                       // 128x64
    uint32_t (*Ks)[68] = (uint32_t(*)[68])(sm_ + 128 * 68);          // 64x64
    uint32_t (*Vs)[72] = (uint32_t(*)[72])(sm_ + 128 * 68 + 64 * 68);// 64x64
    uint32_t (*Ps)[68] = (uint32_t(*)[68])(sm_ + 128 * 68 + 64 * 68 + 64 * 72); // 128x64
    float*    rZs      = (float*)(sm_ + 2 * 128 * 68 + 64 * 68 + 64 * 72);

    const int c = blockIdx.x, ti = blockIdx.y, b = blockIdx.z;
    const int sBeg = c * 8;                    // in 64-wide s-tiles
    const int sCnt = 2 * (ti + 1);
    const int sEnd = min(sCnt, sBeg + 8);
    if (sBeg >= sEnd) return;
    const int t0 = ti * 128;

    const float* q  = &g_qkv[(size_t)b * TT * HH];
    const float* kp = &g_qkv[(size_t)(NTOK + b * TT) * HH];
    const float* vp = &g_qkv[(size_t)(2 * NTOK + b * TT) * HH];
    const float* rz = &g_rZ[b * TT];
    const int tid = threadIdx.x, lane = tid & 31, wid = tid >> 5;
    const int lr = lane >> 2, lc = lane & 3;
    const float scale = rsqrtf((float)CC);

    // QK^T warp layout: 2(m) x 4(n) -> warp tile 64(t) x 16(s)
    const int wmq = (wid >> 2) * 64, wnq = (wid & 3) * 16;
    // PV warp layout: 4(m) x 2(n) -> warp tile 32(t) x 32(h)
    const int wm = (wid >> 1) * 32, wn = (wid & 1) * 32;

    for (int i = tid; i < 2048; i += 256) {                 // Q tile 128x64
        int r = i >> 4, c4 = i & 15;
        float4 v = *(const float4*)&q[(size_t)(t0 + r) * HH + c4 * 4];
        *(uint4*)&Qs[r][c4 * 4] = make_uint4(f2tf(v.x), f2tf(v.y), f2tf(v.z), f2tf(v.w));
    }

    float acc_o[2][4][4] = {};

    for (int s64 = sBeg; s64 < sEnd; s64++) {
        const int s0 = s64 * 64;
        for (int i = tid; i < 1024; i += 256) {             // K,V tiles 64x64
            int r = i >> 4, c4 = i & 15;
            float4 w = *(const float4*)&kp[(size_t)(s0 + r) * HH + c4 * 4];
            *(uint4*)&Ks[r][c4 * 4] = make_uint4(f2tf(w.x), f2tf(w.y), f2tf(w.z), f2tf(w.w));
            float4 v = *(const float4*)&vp[(size_t)(s0 + r) * HH + c4 * 4];
            *(uint4*)&Vs[r][c4 * 4] = make_uint4(f2tf(v.x), f2tf(v.y), f2tf(v.z), f2tf(v.w));
        }
        for (int i = tid; i < 64; i += 256) rZs[i] = rz[s0 + i];
        __syncthreads();

        // --- QK^T: 128x64x64 ---
        float acc_qk[4][2][4] = {};
        #pragma unroll
        for (int ks = 0; ks < 8; ks++) {
            const int k = ks * 8;
            uint32_t a[4][4], bf[2][2];
            #pragma unroll
            for (int mi = 0; mi < 4; mi++) {
                int rb = wmq + mi * 16;
                a[mi][0] = Qs[rb + lr][k + lc];
                a[mi][1] = Qs[rb + lr + 8][k + lc];
                a[mi][2] = Qs[rb + lr][k + lc + 4];
                a[mi][3] = Qs[rb + lr + 8][k + lc + 4];
            }
            #pragma unroll
            for (int ni = 0; ni < 2; ni++) {
                int sb = wnq + ni * 8 + lr;
                bf[ni][0] = Ks[sb][k + lc];
                bf[ni][1] = Ks[sb][k + lc + 4];
            }
            #pragma unroll
            for (int mi = 0; mi < 4; mi++)
                #pragma unroll
                for (int ni = 0; ni < 2; ni++)
                    mma8(acc_qk[mi][ni], a[mi], bf[ni]);
        }

        // --- P = exp(S)*rZ -> smem (tf32) ---
        #pragma unroll
        for (int mi = 0; mi < 4; mi++)
            #pragma unroll
            for (int ni = 0; ni < 2; ni++) {
                int tr = wmq + mi * 16 + lr;
                int sc = wnq + ni * 8 + 2 * lc;
                int tg = t0 + tr, sg = s0 + sc;
                float z0 = rZs[sc], z1 = rZs[sc + 1];
                uint2 u;
                u.x = f2tf((tg >= sg)     ? __expf(acc_qk[mi][ni][0] * scale) * z0 : 0.f);
                u.y = f2tf((tg >= sg + 1) ? __expf(acc_qk[mi][ni][1] * scale) * z1 : 0.f);
                *(uint2*)&Ps[tr][sc] = u;
                u.x = f2tf((tg + 8 >= sg)     ? __expf(acc_qk[mi][ni][2] * scale) * z0 : 0.f);
                u.y = f2tf((tg + 8 >= sg + 1) ? __expf(acc_qk[mi][ni][3] * scale) * z1 : 0.f);
                *(uint2*)&Ps[tr + 8][sc] = u;
            }
        __syncthreads();

        // --- O += P(128x64) @ V(64x64) ---
        #pragma unroll
        for (int ks = 0; ks < 8; ks++) {
            const int k = ks * 8;
            uint32_t a[2][4], bf[4][2];
            #pragma unroll
            for (int mi = 0; mi < 2; mi++) {
                int rb = wm + mi * 16;
                a[mi][0] = Ps[rb + lr][k + lc];
                a[mi][1] = Ps[rb + lr + 8][k + lc];
                a[mi][2] = Ps[rb + lr][k + lc + 4];
                a[mi][3] = Ps[rb + lr + 8][k + lc + 4];
            }
            #pragma unroll
            for (int ni = 0; ni < 4; ni++) {
                int cb = wn + ni * 8 + lr;
                bf[ni][0] = Vs[k + lc][cb];
                bf[ni][1] = Vs[k + lc + 4][cb];
            }
            #pragma unroll
            for (int mi = 0; mi < 2; mi++)
                #pragma unroll
                for (int ni = 0; ni < 4; ni++)
                    mma8(acc_o[mi][ni], a[mi], bf[ni]);
        }
        __syncthreads();
    }

    #pragma unroll
    for (int mi = 0; mi < 2; mi++)
        #pragma unroll
        for (int ni = 0; ni < 4; ni++) {
            int row = b * TT + t0 + wm + mi * 16 + lr;
            int col = wn + ni * 8 + 2 * lc;
            float* o = &out[(size_t)row * HH + col];
            atomicAdd(o,     acc_o[mi][ni][0]);
            atomicAdd(o + 1, acc_o[mi][ni][1]);
            float* o2 = o + 8 * HH;
            atomicAdd(o2,     acc_o[mi][ni][2]);
            atomicAdd(o2 + 1, acc_o[mi][ni][3]);
        }
}

// ---------------------------------------------------------------------------
extern "C" void kernel_launch(void* const* d_in, const int* in_sizes, int n_in,
                              void* d_out, int out_size) {
    const float* x  = (const float*)d_in[0];
    const float* Wq = (const float*)d_in[1];
    const float* Wk = (const float*)d_in[2];
    const float* Wv = (const float*)d_in[3];
    float* out = (float*)d_out;

    const int stats_smem = 2 * 128 * 68 * 4;                              // 69632
    const int pv_smem    = (2 * 128 * 68 + 64 * 68 + 64 * 72) * 4 + 256;  // ~106KB
    cudaFuncSetAttribute(stats_kernel, cudaFuncAttributeMaxDynamicSharedMemorySize, stats_smem);
    cudaFuncSetAttribute(pv_kernel,    cudaFuncAttributeMaxDynamicSharedMemorySize, pv_smem);

    cudaMemsetAsync(d_out, 0, (size_t)out_size * sizeof(float));
    qkv_kernel<<<dim3(NTOK / 128, 3), 256>>>(x, Wq, Wk, Wv);
    zeroZ_kernel<<<NTOK / 256, 256>>>();
    stats_kernel<<<dim3(16, 2, BB), 256, stats_smem>>>();
    recip_kernel<<<NTOK / 256, 256>>>();
    pv_kernel<<<dim3(4, 16, BB), 256, pv_smem>>>(out);
}

// round 4
// speedup vs baseline: 5.0021x; 1.8688x over previous
#include <cuda_runtime.h>
#include <math.h>
#include <stdint.h>

#define BB 8
#define TT 2048
#define CC 384
#define HH 64
#define NTOK (BB * TT)   // 16384

__device__ uint32_t g_qkv[3 * NTOK * HH];         // q | k | v, tf32 bits
__device__ float g_Z[NTOK];                       // per-(b,s) column sum of exp

__device__ __forceinline__ uint32_t f2tf(float f) {
    uint32_t r; asm("cvt.rna.tf32.f32 %0, %1;" : "=r"(r) : "f"(f)); return r;
}
__device__ __forceinline__ float frcp(float f) {
    float r; asm("rcp.approx.f32 %0, %1;" : "=f"(r) : "f"(f)); return r;
}
__device__ __forceinline__ void mma8(float* c, const uint32_t* a, const uint32_t* b) {
    asm volatile(
        "mma.sync.aligned.m16n8k8.row.col.f32.tf32.tf32.f32 "
        "{%0,%1,%2,%3}, {%4,%5,%6,%7}, {%8,%9}, {%0,%1,%2,%3};\n"
        : "+f"(c[0]), "+f"(c[1]), "+f"(c[2]), "+f"(c[3])
        : "r"(a[0]), "r"(a[1]), "r"(a[2]), "r"(a[3]), "r"(b[0]), "r"(b[1]));
}
__device__ __forceinline__ void cpa16(uint32_t s, const void* g) {
    asm volatile("cp.async.cg.shared.global [%0], [%1], 16;" :: "r"(s), "l"(g));
}
__device__ __forceinline__ void cp_commit() { asm volatile("cp.async.commit_group;"); }
template<int N> __device__ __forceinline__ void cp_wait() {
    asm volatile("cp.async.wait_group %0;" :: "n"(N));
}

// ---------------------------------------------------------------------------
// Kernel A: fused QKV projection -> tf32 bits. Also zeroes g_Z.
// grid(NTOK/128, 3), 256 thr.
// ---------------------------------------------------------------------------
__global__ void qkv_kernel(const float* __restrict__ x,
                           const float* __restrict__ Wq,
                           const float* __restrict__ Wk,
                           const float* __restrict__ Wv) {
    __shared__ uint32_t Xs[128][36];   // pad ==4 mod 32
    __shared__ uint32_t Ws[32][72];    // pad ==8 mod 32
    const float* W = (blockIdx.y == 0) ? Wq : ((blockIdx.y == 1) ? Wk : Wv);
    const int r0  = blockIdx.x * 128;
    const int tid = threadIdx.x, lane = tid & 31, wid = tid >> 5;
    const int lr = lane >> 2, lc = lane & 3;
    const int wm = (wid >> 1) * 32, wn = (wid & 1) * 32;

    if (blockIdx.y == 2 && tid < 128) g_Z[blockIdx.x * 128 + tid] = 0.f;

    float acc[2][4][4] = {};
    for (int k0 = 0; k0 < CC; k0 += 32) {
        for (int i = tid; i < 1024; i += 256) {
            int r = i >> 3, c4 = i & 7;
            float4 v = *(const float4*)&x[(size_t)(r0 + r) * CC + k0 + c4 * 4];
            *(uint4*)&Xs[r][c4 * 4] = make_uint4(f2tf(v.x), f2tf(v.y), f2tf(v.z), f2tf(v.w));
        }
        for (int i = tid; i < 512; i += 256) {
            int r = i >> 4, c4 = i & 15;
            float4 v = *(const float4*)&W[(k0 + r) * HH + c4 * 4];
            *(uint4*)&Ws[r][c4 * 4] = make_uint4(f2tf(v.x), f2tf(v.y), f2tf(v.z), f2tf(v.w));
        }
        __syncthreads();
        #pragma unroll
        for (int ks = 0; ks < 4; ks++) {
            const int k = ks * 8;
            uint32_t a[2][4], bf[4][2];
            #pragma unroll
            for (int mi = 0; mi < 2; mi++) {
                int rb = wm + mi * 16;
                a[mi][0] = Xs[rb + lr][k + lc];
                a[mi][1] = Xs[rb + lr + 8][k + lc];
                a[mi][2] = Xs[rb + lr][k + lc + 4];
                a[mi][3] = Xs[rb + lr + 8][k + lc + 4];
            }
            #pragma unroll
            for (int ni = 0; ni < 4; ni++) {
                int cb = wn + ni * 8 + lr;
                bf[ni][0] = Ws[k + lc][cb];
                bf[ni][1] = Ws[k + lc + 4][cb];
            }
            #pragma unroll
            for (int mi = 0; mi < 2; mi++)
                #pragma unroll
                for (int ni = 0; ni < 4; ni++)
                    mma8(acc[mi][ni], a[mi], bf[ni]);
        }
        __syncthreads();
    }

    uint32_t* dst = &g_qkv[(size_t)blockIdx.y * NTOK * HH];
    #pragma unroll
    for (int mi = 0; mi < 2; mi++)
        #pragma unroll
        for (int ni = 0; ni < 4; ni++) {
            int row = r0 + wm + mi * 16 + lr;
            int col = wn + ni * 8 + 2 * lc;
            *(uint2*)&dst[(size_t)row * HH + col] =
                make_uint2(f2tf(acc[mi][ni][0]), f2tf(acc[mi][ni][1]));
            *(uint2*)&dst[(size_t)(row + 8) * HH + col] =
                make_uint2(f2tf(acc[mi][ni][2]), f2tf(acc[mi][ni][3]));
        }
}

// ---------------------------------------------------------------------------
// Kernel B: Z[s] = sum_{t>=s} exp(scale*q_t.k_s). cp.async double-buffered Q.
// grid(16 s-tiles, 4 t-chunks, B), 256 thr, K tile persistent.
// smem: Ks[128][68] + Qs[2][128][68]
// ---------------------------------------------------------------------------
__global__ void __launch_bounds__(256, 2) stats_kernel() {
    extern __shared__ uint32_t sm_[];
    uint32_t (*Ks)[68]      = (uint32_t(*)[68])sm_;
    uint32_t (*Qs)[128][68] = (uint32_t(*)[128][68])(sm_ + 128 * 68);
    const uint32_t sbase = (uint32_t)__cvta_generic_to_shared(sm_);
    const uint32_t KS_B = sbase, QS_B = sbase + 128 * 68 * 4;

    const int si = blockIdx.x, c = blockIdx.y, b = blockIdx.z;
    const int tBeg = max(si, c * 4), tEnd = min(16, c * 4 + 4);
    if (tBeg >= tEnd) return;
    const int s0 = si * 128;
    const uint32_t* q  = &g_qkv[(size_t)b * TT * HH];
    const uint32_t* kp = &g_qkv[(size_t)(NTOK + b * TT) * HH];
    const int tid = threadIdx.x, lane = tid & 31, wid = tid >> 5;
    const int lr = lane >> 2, lc = lane & 3;
    const int wm = (wid >> 2) * 64, wn = (wid & 3) * 32;
    const float scale = rsqrtf((float)CC);

    // prologue: K tile + first Q tile, one commit group
    for (int i = tid; i < 2048; i += 256) {
        int r = i >> 4, c4 = i & 15;
        cpa16(KS_B + (r * 68 + c4 * 4) * 4, kp + (size_t)(s0 + r) * HH + c4 * 4);
        cpa16(QS_B + (r * 68 + c4 * 4) * 4, q + (size_t)(tBeg * 128 + r) * HH + c4 * 4);
    }
    cp_commit();

    float colsum[4][2] = {};
    for (int ti = tBeg; ti < tEnd; ti++) {
        const int st = (ti - tBeg) & 1;
        if (ti + 1 < tEnd) {
            const uint32_t dstB = QS_B + (st ^ 1) * 128 * 68 * 4;
            for (int i = tid; i < 2048; i += 256) {
                int r = i >> 4, c4 = i & 15;
                cpa16(dstB + (r * 68 + c4 * 4) * 4,
                      q + (size_t)((ti + 1) * 128 + r) * HH + c4 * 4);
            }
            cp_commit();
            cp_wait<1>();
        } else {
            cp_wait<0>();
        }
        __syncthreads();

        const int t0 = ti * 128;
        float acc[4][4][4] = {};
        #pragma unroll
        for (int ks = 0; ks < 8; ks++) {
            const int k = ks * 8;
            uint32_t a[4][4], bf[4][2];
            #pragma unroll
            for (int mi = 0; mi < 4; mi++) {
                int rb = wm + mi * 16;
                a[mi][0] = Qs[st][rb + lr][k + lc];
                a[mi][1] = Qs[st][rb + lr + 8][k + lc];
                a[mi][2] = Qs[st][rb + lr][k + lc + 4];
                a[mi][3] = Qs[st][rb + lr + 8][k + lc + 4];
            }
            #pragma unroll
            for (int ni = 0; ni < 4; ni++) {
                int sb = wn + ni * 8 + lr;
                bf[ni][0] = Ks[sb][k + lc];
                bf[ni][1] = Ks[sb][k + lc + 4];
            }
            #pragma unroll
            for (int mi = 0; mi < 4; mi++)
                #pragma unroll
                for (int ni = 0; ni < 4; ni++)
                    mma8(acc[mi][ni], a[mi], bf[ni]);
        }

        #pragma unroll
        for (int mi = 0; mi < 4; mi++)
            #pragma unroll
            for (int ni = 0; ni < 4; ni++) {
                int tg = t0 + wm + mi * 16 + lr;
                int sg = s0 + wn + ni * 8 + 2 * lc;
                float e0 = (tg >= sg)         ? __expf(acc[mi][ni][0] * scale) : 0.f;
                float e1 = (tg >= sg + 1)     ? __expf(acc[mi][ni][1] * scale) : 0.f;
                float e2 = (tg + 8 >= sg)     ? __expf(acc[mi][ni][2] * scale) : 0.f;
                float e3 = (tg + 8 >= sg + 1) ? __expf(acc[mi][ni][3] * scale) : 0.f;
                colsum[ni][0] += e0 + e2;
                colsum[ni][1] += e1 + e3;
            }
        __syncthreads();
    }

    #pragma unroll
    for (int ni = 0; ni < 4; ni++)
        #pragma unroll
        for (int jj = 0; jj < 2; jj++) {
            float v = colsum[ni][jj];
            v += __shfl_xor_sync(0xffffffffu, v, 16);
            v += __shfl_xor_sync(0xffffffffu, v, 8);
            v += __shfl_xor_sync(0xffffffffu, v, 4);
            colsum[ni][jj] = v;
        }
    if (lr == 0) {
        #pragma unroll
        for (int ni = 0; ni < 4; ni++) {
            int sg = s0 + wn + ni * 8 + 2 * lc;
            atomicAdd(&g_Z[b * TT + sg],     colsum[ni][0]);
            atomicAdd(&g_Z[b * TT + sg + 1], colsum[ni][1]);
        }
    }
}

// ---------------------------------------------------------------------------
// Kernel D: fused recompute QK^T -> P -> PV. cp.async double-buffered K/V/Z.
// grid(8 s-chunks of 4x64, 16 t-tiles, B), 256 thr.
// smem: Qs[128][68] Ps[128][68] Ks[2][64][68] Vs[2][64][72] Zs[2][64] rZs[64]
// ---------------------------------------------------------------------------
__global__ void __launch_bounds__(256, 1) pv_kernel(float* __restrict__ out) {
    extern __shared__ uint32_t sm_[];
    uint32_t (*Qs)[68]     = (uint32_t(*)[68])sm_;
    uint32_t (*Ps)[68]     = (uint32_t(*)[68])(sm_ + 8704);
    uint32_t (*Ks)[64][68] = (uint32_t(*)[64][68])(sm_ + 17408);
    uint32_t (*Vs)[64][72] = (uint32_t(*)[64][72])(sm_ + 26112);
    float    (*Zs)[64]     = (float(*)[64])(sm_ + 35328);
    float*    rZs          = (float*)(sm_ + 35456);
    const uint32_t sbase = (uint32_t)__cvta_generic_to_shared(sm_);
    const uint32_t QS_B = sbase, KS_B = sbase + 17408 * 4,
                   VS_B = sbase + 26112 * 4, ZS_B = sbase + 35328 * 4;

    const int c = blockIdx.x, ti = blockIdx.y, b = blockIdx.z;
    const int sBeg = c * 4;
    const int sEnd = min(sBeg + 4, 2 * (ti + 1));
    if (sBeg >= sEnd) return;
    const int t0 = ti * 128;

    const uint32_t* q  = &g_qkv[(size_t)b * TT * HH];
    const uint32_t* kp = &g_qkv[(size_t)(NTOK + b * TT) * HH];
    const uint32_t* vp = &g_qkv[(size_t)(2 * NTOK + b * TT) * HH];
    const float* Zg = &g_Z[b * TT];
    const int tid = threadIdx.x, lane = tid & 31, wid = tid >> 5;
    const int lr = lane >> 2, lc = lane & 3;
    const float scale = rsqrtf((float)CC);
    const int wmq = (wid >> 2) * 64, wnq = (wid & 3) * 16;   // QK layout
    const int wm  = (wid >> 1) * 32, wn  = (wid & 1) * 32;   // PV layout

    // prologue group: Q tile + K/V/Z of first s-tile
    for (int i = tid; i < 2048; i += 256) {
        int r = i >> 4, c4 = i & 15;
        cpa16(QS_B + (r * 68 + c4 * 4) * 4, q + (size_t)(t0 + r) * HH + c4 * 4);
    }
    {
        const int s0 = sBeg * 64;
        for (int i = tid; i < 1024; i += 256) {
            int r = i >> 4, c4 = i & 15;
            cpa16(KS_B + (r * 68 + c4 * 4) * 4, kp + (size_t)(s0 + r) * HH + c4 * 4);
            cpa16(VS_B + (r * 72 + c4 * 4) * 4, vp + (size_t)(s0 + r) * HH + c4 * 4);
        }
        if (tid < 16) cpa16(ZS_B + tid * 16, Zg + s0 + tid * 4);
    }
    cp_commit();

    float acc_o[2][4][4] = {};

    for (int s64 = sBeg; s64 < sEnd; s64++) {
        const int st = (s64 - sBeg) & 1;
        if (s64 + 1 < sEnd) {
            const int s0n = (s64 + 1) * 64;
            const uint32_t kD = KS_B + (st ^ 1) * 64 * 68 * 4;
            const uint32_t vD = VS_B + (st ^ 1) * 64 * 72 * 4;
            for (int i = tid; i < 1024; i += 256) {
                int r = i >> 4, c4 = i & 15;
                cpa16(kD + (r * 68 + c4 * 4) * 4, kp + (size_t)(s0n + r) * HH + c4 * 4);
                cpa16(vD + (r * 72 + c4 * 4) * 4, vp + (size_t)(s0n + r) * HH + c4 * 4);
            }
            if (tid < 16) cpa16(ZS_B + ((st ^ 1) * 64 + tid * 4) * 4, Zg + s0n + tid * 4);
            cp_commit();
            cp_wait<1>();
        } else {
            cp_wait<0>();
        }
        // threads 0..15 own the Z chunks they loaded -> safe pre-barrier rcp
        if (tid < 16) {
            #pragma unroll
            for (int j = 0; j < 4; j++)
                rZs[tid * 4 + j] = frcp(Zs[st][tid * 4 + j]);
        }
        __syncthreads();

        const int s0 = s64 * 64;
        // --- QK^T: 128x64x64 ---
        float acc_qk[4][2][4] = {};
        #pragma unroll
        for (int ks = 0; ks < 8; ks++) {
            const int k = ks * 8;
            uint32_t a[4][4], bf[2][2];
            #pragma unroll
            for (int mi = 0; mi < 4; mi++) {
                int rb = wmq + mi * 16;
                a[mi][0] = Qs[rb + lr][k + lc];
                a[mi][1] = Qs[rb + lr + 8][k + lc];
                a[mi][2] = Qs[rb + lr][k + lc + 4];
                a[mi][3] = Qs[rb + lr + 8][k + lc + 4];
            }
            #pragma unroll
            for (int ni = 0; ni < 2; ni++) {
                int sb = wnq + ni * 8 + lr;
                bf[ni][0] = Ks[st][sb][k + lc];
                bf[ni][1] = Ks[st][sb][k + lc + 4];
            }
            #pragma unroll
            for (int mi = 0; mi < 4; mi++)
                #pragma unroll
                for (int ni = 0; ni < 2; ni++)
                    mma8(acc_qk[mi][ni], a[mi], bf[ni]);
        }

        // --- P = exp(S)*rZ -> smem ---
        #pragma unroll
        for (int mi = 0; mi < 4; mi++)
            #pragma unroll
            for (int ni = 0; ni < 2; ni++) {
                int tr = wmq + mi * 16 + lr;
                int sc = wnq + ni * 8 + 2 * lc;
                int tg = t0 + tr, sg = s0 + sc;
                float z0 = rZs[sc], z1 = rZs[sc + 1];
                uint2 u;
                u.x = f2tf((tg >= sg)     ? __expf(acc_qk[mi][ni][0] * scale) * z0 : 0.f);
                u.y = f2tf((tg >= sg + 1) ? __expf(acc_qk[mi][ni][1] * scale) * z1 : 0.f);
                *(uint2*)&Ps[tr][sc] = u;
                u.x = f2tf((tg + 8 >= sg)     ? __expf(acc_qk[mi][ni][2] * scale) * z0 : 0.f);
                u.y = f2tf((tg + 8 >= sg + 1) ? __expf(acc_qk[mi][ni][3] * scale) * z1 : 0.f);
                *(uint2*)&Ps[tr + 8][sc] = u;
            }
        __syncthreads();

        // --- O += P(128x64) @ V(64x64) ---
        #pragma unroll
        for (int ks = 0; ks < 8; ks++) {
            const int k = ks * 8;
            uint32_t a[2][4], bf[4][2];
            #pragma unroll
            for (int mi = 0; mi < 2; mi++) {
                int rb = wm + mi * 16;
                a[mi][0] = Ps[rb + lr][k + lc];
                a[mi][1] = Ps[rb + lr + 8][k + lc];
                a[mi][2] = Ps[rb + lr][k + lc + 4];
                a[mi][3] = Ps[rb + lr + 8][k + lc + 4];
            }
            #pragma unroll
            for (int ni = 0; ni < 4; ni++) {
                int cb = wn + ni * 8 + lr;
                bf[ni][0] = Vs[st][k + lc][cb];
                bf[ni][1] = Vs[st][k + lc + 4][cb];
            }
            #pragma unroll
            for (int mi = 0; mi < 2; mi++)
                #pragma unroll
                for (int ni = 0; ni < 4; ni++)
                    mma8(acc_o[mi][ni], a[mi], bf[ni]);
        }
        __syncthreads();
    }

    #pragma unroll
    for (int mi = 0; mi < 2; mi++)
        #pragma unroll
        for (int ni = 0; ni < 4; ni++) {
            int row = b * TT + t0 + wm + mi * 16 + lr;
            int col = wn + ni * 8 + 2 * lc;
            float* o = &out[(size_t)row * HH + col];
            atomicAdd(o,     acc_o[mi][ni][0]);
            atomicAdd(o + 1, acc_o[mi][ni][1]);
            float* o2 = o + 8 * HH;
            atomicAdd(o2,     acc_o[mi][ni][2]);
            atomicAdd(o2 + 1, acc_o[mi][ni][3]);
        }
}

// ---------------------------------------------------------------------------
extern "C" void kernel_launch(void* const* d_in, const int* in_sizes, int n_in,
                              void* d_out, int out_size) {
    const float* x  = (const float*)d_in[0];
    const float* Wq = (const float*)d_in[1];
    const float* Wk = (const float*)d_in[2];
    const float* Wv = (const float*)d_in[3];
    float* out = (float*)d_out;

    const int stats_smem = (128 * 68 + 2 * 128 * 68) * 4;   // 104448
    const int pv_smem    = 35520 * 4;                       // 142080
    cudaFuncSetAttribute(stats_kernel, cudaFuncAttributeMaxDynamicSharedMemorySize, stats_smem);
    cudaFuncSetAttribute(pv_kernel,    cudaFuncAttributeMaxDynamicSharedMemorySize, pv_smem);

    cudaMemsetAsync(d_out, 0, (size_t)out_size * sizeof(float));
    qkv_kernel<<<dim3(NTOK / 128, 3), 256>>>(x, Wq, Wk, Wv);
    stats_kernel<<<dim3(16, 4, BB), 256, stats_smem>>>();
    pv_kernel<<<dim3(8, 16, BB), 256, pv_smem>>>(out);
}

// round 5
// speedup vs baseline: 5.3818x; 1.0759x over previous
#include <cuda_runtime.h>
#include <math.h>
#include <stdint.h>

#define BB 8
#define TT 2048
#define CC 384
#define HH 64
#define NTOK (BB * TT)   // 16384

__device__ uint32_t g_qkv[3 * NTOK * HH];         // q | k | v, tf32 bits
__device__ float g_Z[NTOK];                       // per-(b,s) column sum of exp

__device__ __forceinline__ uint32_t f2tf(float f) {
    uint32_t r; asm("cvt.rna.tf32.f32 %0, %1;" : "=r"(r) : "f"(f)); return r;
}
__device__ __forceinline__ float frcp(float f) {
    float r; asm("rcp.approx.f32 %0, %1;" : "=f"(r) : "f"(f)); return r;
}
__device__ __forceinline__ void mma8(float* c, const uint32_t* a, const uint32_t* b) {
    asm volatile(
        "mma.sync.aligned.m16n8k8.row.col.f32.tf32.tf32.f32 "
        "{%0,%1,%2,%3}, {%4,%5,%6,%7}, {%8,%9}, {%0,%1,%2,%3};\n"
        : "+f"(c[0]), "+f"(c[1]), "+f"(c[2]), "+f"(c[3])
        : "r"(a[0]), "r"(a[1]), "r"(a[2]), "r"(a[3]), "r"(b[0]), "r"(b[1]));
}
__device__ __forceinline__ void cpa16(uint32_t s, const void* g) {
    asm volatile("cp.async.cg.shared.global [%0], [%1], 16;" :: "r"(s), "l"(g));
}
__device__ __forceinline__ void cp_commit() { asm volatile("cp.async.commit_group;"); }
template<int N> __device__ __forceinline__ void cp_wait() {
    asm volatile("cp.async.wait_group %0;" :: "n"(N));
}

// ---------------------------------------------------------------------------
// Kernel A: fused QKV projection, one block does q,k,v for a 128-row stripe.
// grid(128), 256 thr. cp.async double-buffered X(128x32) + W(3x32x64) tiles.
// Warps 4(m) x 2(n): warp tile 32x32 per output. Also zeroes g_Z.
// ---------------------------------------------------------------------------
__global__ void __launch_bounds__(256, 1) qkv_kernel(
        const float* __restrict__ x,
        const float* __restrict__ Wq,
        const float* __restrict__ Wk,
        const float* __restrict__ Wv) {
    __shared__ float Xs[2][128][36];      // pad 36 (==4 mod 32)
    __shared__ float Ws[2][3][32][72];    // pad 72 (==8 mod 32)
    const uint32_t XB = (uint32_t)__cvta_generic_to_shared(&Xs[0][0][0]);
    const uint32_t WB = (uint32_t)__cvta_generic_to_shared(&Ws[0][0][0][0]);
    const float* Wmat[3] = {Wq, Wk, Wv};

    const int r0  = blockIdx.x * 128;
    const int tid = threadIdx.x, lane = tid & 31, wid = tid >> 5;
    const int lr = lane >> 2, lc = lane & 3;
    const int wm = (wid >> 1) * 32, wn = (wid & 1) * 32;

    if (tid < 128) g_Z[blockIdx.x * 128 + tid] = 0.f;

    // prologue: k0 = 0 tiles
    for (int i = tid; i < 1024; i += 256) {
        int r = i >> 3, c4 = i & 7;
        cpa16(XB + (r * 36 + c4 * 4) * 4, x + (size_t)(r0 + r) * CC + c4 * 4);
    }
    for (int i = tid; i < 1536; i += 256) {
        int w = i >> 9, j = i & 511, r = j >> 4, c4 = j & 15;
        cpa16(WB + ((w * 32 + r) * 72 + c4 * 4) * 4, Wmat[w] + (size_t)r * HH + c4 * 4);
    }
    cp_commit();

    float acc[3][2][4][4] = {};
    for (int k0 = 0; k0 < CC; k0 += 32) {
        const int st = (k0 >> 5) & 1;
        if (k0 + 32 < CC) {
            const uint32_t xD = XB + (st ^ 1) * 128 * 36 * 4;
            const uint32_t wD = WB + (st ^ 1) * 3 * 32 * 72 * 4;
            for (int i = tid; i < 1024; i += 256) {
                int r = i >> 3, c4 = i & 7;
                cpa16(xD + (r * 36 + c4 * 4) * 4,
                      x + (size_t)(r0 + r) * CC + k0 + 32 + c4 * 4);
            }
            for (int i = tid; i < 1536; i += 256) {
                int w = i >> 9, j = i & 511, r = j >> 4, c4 = j & 15;
                cpa16(wD + ((w * 32 + r) * 72 + c4 * 4) * 4,
                      Wmat[w] + (size_t)(k0 + 32 + r) * HH + c4 * 4);
            }
            cp_commit();
            cp_wait<1>();
        } else {
            cp_wait<0>();
        }
        __syncthreads();

        #pragma unroll
        for (int ks = 0; ks < 4; ks++) {
            const int k = ks * 8;
            uint32_t a[2][4];
            #pragma unroll
            for (int mi = 0; mi < 2; mi++) {
                int rb = wm + mi * 16;
                a[mi][0] = f2tf(Xs[st][rb + lr][k + lc]);
                a[mi][1] = f2tf(Xs[st][rb + lr + 8][k + lc]);
                a[mi][2] = f2tf(Xs[st][rb + lr][k + lc + 4]);
                a[mi][3] = f2tf(Xs[st][rb + lr + 8][k + lc + 4]);
            }
            #pragma unroll
            for (int w = 0; w < 3; w++) {
                uint32_t bf[4][2];
                #pragma unroll
                for (int ni = 0; ni < 4; ni++) {
                    int cb = wn + ni * 8 + lr;
                    bf[ni][0] = f2tf(Ws[st][w][k + lc][cb]);
                    bf[ni][1] = f2tf(Ws[st][w][k + lc + 4][cb]);
                }
                #pragma unroll
                for (int mi = 0; mi < 2; mi++)
                    #pragma unroll
                    for (int ni = 0; ni < 4; ni++)
                        mma8(acc[w][mi][ni], a[mi], bf[ni]);
            }
        }
        __syncthreads();
    }

    #pragma unroll
    for (int w = 0; w < 3; w++) {
        uint32_t* dst = &g_qkv[(size_t)w * NTOK * HH];
        #pragma unroll
        for (int mi = 0; mi < 2; mi++)
            #pragma unroll
            for (int ni = 0; ni < 4; ni++) {
                int row = r0 + wm + mi * 16 + lr;
                int col = wn + ni * 8 + 2 * lc;
                *(uint2*)&dst[(size_t)row * HH + col] =
                    make_uint2(f2tf(acc[w][mi][ni][0]), f2tf(acc[w][mi][ni][1]));
                *(uint2*)&dst[(size_t)(row + 8) * HH + col] =
                    make_uint2(f2tf(acc[w][mi][ni][2]), f2tf(acc[w][mi][ni][3]));
            }
    }
}

// ---------------------------------------------------------------------------
// Kernel B: Z[s] = sum_{t>=s} exp(scale*q_t.k_s). cp.async double-buffered Q.
// grid(16 s-tiles, 4 t-chunks, B), 256 thr, K tile persistent.
// ---------------------------------------------------------------------------
__global__ void __launch_bounds__(256, 2) stats_kernel() {
    extern __shared__ uint32_t sm_[];
    uint32_t (*Ks)[68]      = (uint32_t(*)[68])sm_;
    uint32_t (*Qs)[128][68] = (uint32_t(*)[128][68])(sm_ + 128 * 68);
    const uint32_t sbase = (uint32_t)__cvta_generic_to_shared(sm_);
    const uint32_t KS_B = sbase, QS_B = sbase + 128 * 68 * 4;

    const int si = blockIdx.x, c = blockIdx.y, b = blockIdx.z;
    const int tBeg = max(si, c * 4), tEnd = min(16, c * 4 + 4);
    if (tBeg >= tEnd) return;
    const int s0 = si * 128;
    const uint32_t* q  = &g_qkv[(size_t)b * TT * HH];
    const uint32_t* kp = &g_qkv[(size_t)(NTOK + b * TT) * HH];
    const int tid = threadIdx.x, lane = tid & 31, wid = tid >> 5;
    const int lr = lane >> 2, lc = lane & 3;
    const int wm = (wid >> 2) * 64, wn = (wid & 3) * 32;
    const float scale = rsqrtf((float)CC);

    for (int i = tid; i < 2048; i += 256) {
        int r = i >> 4, c4 = i & 15;
        cpa16(KS_B + (r * 68 + c4 * 4) * 4, kp + (size_t)(s0 + r) * HH + c4 * 4);
        cpa16(QS_B + (r * 68 + c4 * 4) * 4, q + (size_t)(tBeg * 128 + r) * HH + c4 * 4);
    }
    cp_commit();

    float colsum[4][2] = {};
    for (int ti = tBeg; ti < tEnd; ti++) {
        const int st = (ti - tBeg) & 1;
        if (ti + 1 < tEnd) {
            const uint32_t dstB = QS_B + (st ^ 1) * 128 * 68 * 4;
            for (int i = tid; i < 2048; i += 256) {
                int r = i >> 4, c4 = i & 15;
                cpa16(dstB + (r * 68 + c4 * 4) * 4,
                      q + (size_t)((ti + 1) * 128 + r) * HH + c4 * 4);
            }
            cp_commit();
            cp_wait<1>();
        } else {
            cp_wait<0>();
        }
        __syncthreads();

        const int t0 = ti * 128;
        float acc[4][4][4] = {};
        #pragma unroll
        for (int ks = 0; ks < 8; ks++) {
            const int k = ks * 8;
            uint32_t a[4][4], bf[4][2];
            #pragma unroll
            for (int mi = 0; mi < 4; mi++) {
                int rb = wm + mi * 16;
                a[mi][0] = Qs[st][rb + lr][k + lc];
                a[mi][1] = Qs[st][rb + lr + 8][k + lc];
                a[mi][2] = Qs[st][rb + lr][k + lc + 4];
                a[mi][3] = Qs[st][rb + lr + 8][k + lc + 4];
            }
            #pragma unroll
            for (int ni = 0; ni < 4; ni++) {
                int sb = wn + ni * 8 + lr;
                bf[ni][0] = Ks[sb][k + lc];
                bf[ni][1] = Ks[sb][k + lc + 4];
            }
            #pragma unroll
            for (int mi = 0; mi < 4; mi++)
                #pragma unroll
                for (int ni = 0; ni < 4; ni++)
                    mma8(acc[mi][ni], a[mi], bf[ni]);
        }

        #pragma unroll
        for (int mi = 0; mi < 4; mi++)
            #pragma unroll
            for (int ni = 0; ni < 4; ni++) {
                int tg = t0 + wm + mi * 16 + lr;
                int sg = s0 + wn + ni * 8 + 2 * lc;
                float e0 = (tg >= sg)         ? __expf(acc[mi][ni][0] * scale) : 0.f;
                float e1 = (tg >= sg + 1)     ? __expf(acc[mi][ni][1] * scale) : 0.f;
                float e2 = (tg + 8 >= sg)     ? __expf(acc[mi][ni][2] * scale) : 0.f;
                float e3 = (tg + 8 >= sg + 1) ? __expf(acc[mi][ni][3] * scale) : 0.f;
                colsum[ni][0] += e0 + e2;
                colsum[ni][1] += e1 + e3;
            }
        __syncthreads();
    }

    #pragma unroll
    for (int ni = 0; ni < 4; ni++)
        #pragma unroll
        for (int jj = 0; jj < 2; jj++) {
            float v = colsum[ni][jj];
            v += __shfl_xor_sync(0xffffffffu, v, 16);
            v += __shfl_xor_sync(0xffffffffu, v, 8);
            v += __shfl_xor_sync(0xffffffffu, v, 4);
            colsum[ni][jj] = v;
        }
    if (lr == 0) {
        #pragma unroll
        for (int ni = 0; ni < 4; ni++) {
            int sg = s0 + wn + ni * 8 + 2 * lc;
            atomicAdd(&g_Z[b * TT + sg],     colsum[ni][0]);
            atomicAdd(&g_Z[b * TT + sg + 1], colsum[ni][1]);
        }
    }
}

// ---------------------------------------------------------------------------
// Kernel D: fused recompute QK^T -> P -> PV. cp.async double-buffered K/V/Z.
// grid(8 s-chunks of 4x64, 16 t-tiles, B), 256 thr.
// ---------------------------------------------------------------------------
__global__ void __launch_bounds__(256, 1) pv_kernel(float* __restrict__ out) {
    extern __shared__ uint32_t sm_[];
    uint32_t (*Qs)[68]     = (uint32_t(*)[68])sm_;
    uint32_t (*Ps)[68]     = (uint32_t(*)[68])(sm_ + 8704);
    uint32_t (*Ks)[64][68] = (uint32_t(*)[64][68])(sm_ + 17408);
    uint32_t (*Vs)[64][72] = (uint32_t(*)[64][72])(sm_ + 26112);
    float    (*Zs)[64]     = (float(*)[64])(sm_ + 35328);
    float*    rZs          = (float*)(sm_ + 35456);
    const uint32_t sbase = (uint32_t)__cvta_generic_to_shared(sm_);
    const uint32_t QS_B = sbase, KS_B = sbase + 17408 * 4,
                   VS_B = sbase + 26112 * 4, ZS_B = sbase + 35328 * 4;

    const int c = blockIdx.x, ti = blockIdx.y, b = blockIdx.z;
    const int sBeg = c * 4;
    const int sEnd = min(sBeg + 4, 2 * (ti + 1));
    if (sBeg >= sEnd) return;
    const int t0 = ti * 128;

    const uint32_t* q  = &g_qkv[(size_t)b * TT * HH];
    const uint32_t* kp = &g_qkv[(size_t)(NTOK + b * TT) * HH];
    const uint32_t* vp = &g_qkv[(size_t)(2 * NTOK + b * TT) * HH];
    const float* Zg = &g_Z[b * TT];
    const int tid = threadIdx.x, lane = tid & 31, wid = tid >> 5;
    const int lr = lane >> 2, lc = lane & 3;
    const float scale = rsqrtf((float)CC);
    const int wmq = (wid >> 2) * 64, wnq = (wid & 3) * 16;
    const int wm  = (wid >> 1) * 32, wn  = (wid & 1) * 32;

    for (int i = tid; i < 2048; i += 256) {
        int r = i >> 4, c4 = i & 15;
        cpa16(QS_B + (r * 68 + c4 * 4) * 4, q + (size_t)(t0 + r) * HH + c4 * 4);
    }
    {
        const int s0 = sBeg * 64;
        for (int i = tid; i < 1024; i += 256) {
            int r = i >> 4, c4 = i & 15;
            cpa16(KS_B + (r * 68 + c4 * 4) * 4, kp + (size_t)(s0 + r) * HH + c4 * 4);
            cpa16(VS_B + (r * 72 + c4 * 4) * 4, vp + (size_t)(s0 + r) * HH + c4 * 4);
        }
        if (tid < 16) cpa16(ZS_B + tid * 16, Zg + s0 + tid * 4);
    }
    cp_commit();

    float acc_o[2][4][4] = {};

    for (int s64 = sBeg; s64 < sEnd; s64++) {
        const int st = (s64 - sBeg) & 1;
        if (s64 + 1 < sEnd) {
            const int s0n = (s64 + 1) * 64;
            const uint32_t kD = KS_B + (st ^ 1) * 64 * 68 * 4;
            const uint32_t vD = VS_B + (st ^ 1) * 64 * 72 * 4;
            for (int i = tid; i < 1024; i += 256) {
                int r = i >> 4, c4 = i & 15;
                cpa16(kD + (r * 68 + c4 * 4) * 4, kp + (size_t)(s0n + r) * HH + c4 * 4);
                cpa16(vD + (r * 72 + c4 * 4) * 4, vp + (size_t)(s0n + r) * HH + c4 * 4);
            }
            if (tid < 16) cpa16(ZS_B + ((st ^ 1) * 64 + tid * 4) * 4, Zg + s0n + tid * 4);
            cp_commit();
            cp_wait<1>();
        } else {
            cp_wait<0>();
        }
        if (tid < 16) {
            #pragma unroll
            for (int j = 0; j < 4; j++)
                rZs[tid * 4 + j] = frcp(Zs[st][tid * 4 + j]);
        }
        __syncthreads();

        const int s0 = s64 * 64;
        float acc_qk[4][2][4] = {};
        #pragma unroll
        for (int ks = 0; ks < 8; ks++) {
            const int k = ks * 8;
            uint32_t a[4][4], bf[2][2];
            #pragma unroll
            for (int mi = 0; mi < 4; mi++) {
                int rb = wmq + mi * 16;
                a[mi][0] = Qs[rb + lr][k + lc];
                a[mi][1] = Qs[rb + lr + 8][k + lc];
                a[mi][2] = Qs[rb + lr][k + lc + 4];
                a[mi][3] = Qs[rb + lr + 8][k + lc + 4];
            }
            #pragma unroll
            for (int ni = 0; ni < 2; ni++) {
                int sb = wnq + ni * 8 + lr;
                bf[ni][0] = Ks[st][sb][k + lc];
                bf[ni][1] = Ks[st][sb][k + lc + 4];
            }
            #pragma unroll
            for (int mi = 0; mi < 4; mi++)
                #pragma unroll
                for (int ni = 0; ni < 2; ni++)
                    mma8(acc_qk[mi][ni], a[mi], bf[ni]);
        }

        #pragma unroll
        for (int mi = 0; mi < 4; mi++)
            #pragma unroll
            for (int ni = 0; ni < 2; ni++) {
                int tr = wmq + mi * 16 + lr;
                int sc = wnq + ni * 8 + 2 * lc;
                int tg = t0 + tr, sg = s0 + sc;
                float z0 = rZs[sc], z1 = rZs[sc + 1];
                uint2 u;
                u.x = f2tf((tg >= sg)     ? __expf(acc_qk[mi][ni][0] * scale) * z0 : 0.f);
                u.y = f2tf((tg >= sg + 1) ? __expf(acc_qk[mi][ni][1] * scale) * z1 : 0.f);
                *(uint2*)&Ps[tr][sc] = u;
                u.x = f2tf((tg + 8 >= sg)     ? __expf(acc_qk[mi][ni][2] * scale) * z0 : 0.f);
                u.y = f2tf((tg + 8 >= sg + 1) ? __expf(acc_qk[mi][ni][3] * scale) * z1 : 0.f);
                *(uint2*)&Ps[tr + 8][sc] = u;
            }
        __syncthreads();

        #pragma unroll
        for (int ks = 0; ks < 8; ks++) {
            const int k = ks * 8;
            uint32_t a[2][4], bf[4][2];
            #pragma unroll
            for (int mi = 0; mi < 2; mi++) {
                int rb = wm + mi * 16;
                a[mi][0] = Ps[rb + lr][k + lc];
                a[mi][1] = Ps[rb + lr + 8][k + lc];
                a[mi][2] = Ps[rb + lr][k + lc + 4];
                a[mi][3] = Ps[rb + lr + 8][k + lc + 4];
            }
            #pragma unroll
            for (int ni = 0; ni < 4; ni++) {
                int cb = wn + ni * 8 + lr;
                bf[ni][0] = Vs[st][k + lc][cb];
                bf[ni][1] = Vs[st][k + lc + 4][cb];
            }
            #pragma unroll
            for (int mi = 0; mi < 2; mi++)
                #pragma unroll
                for (int ni = 0; ni < 4; ni++)
                    mma8(acc_o[mi][ni], a[mi], bf[ni]);
        }
        __syncthreads();
    }

    #pragma unroll
    for (int mi = 0; mi < 2; mi++)
        #pragma unroll
        for (int ni = 0; ni < 4; ni++) {
            int row = b * TT + t0 + wm + mi * 16 + lr;
            int col = wn + ni * 8 + 2 * lc;
            float* o = &out[(size_t)row * HH + col];
            atomicAdd(o,     acc_o[mi][ni][0]);
            atomicAdd(o + 1, acc_o[mi][ni][1]);
            float* o2 = o + 8 * HH;
            atomicAdd(o2,     acc_o[mi][ni][2]);
            atomicAdd(o2 + 1, acc_o[mi][ni][3]);
        }
}

// ---------------------------------------------------------------------------
extern "C" void kernel_launch(void* const* d_in, const int* in_sizes, int n_in,
                              void* d_out, int out_size) {
    const float* x  = (const float*)d_in[0];
    const float* Wq = (const float*)d_in[1];
    const float* Wk = (const float*)d_in[2];
    const float* Wv = (const float*)d_in[3];
    float* out = (float*)d_out;

    const int stats_smem = (128 * 68 + 2 * 128 * 68) * 4;   // 104448
    const int pv_smem    = 35520 * 4;                       // 142080
    cudaFuncSetAttribute(stats_kernel, cudaFuncAttributeMaxDynamicSharedMemorySize, stats_smem);
    cudaFuncSetAttribute(pv_kernel,    cudaFuncAttributeMaxDynamicSharedMemorySize, pv_smem);

    cudaMemsetAsync(d_out, 0, (size_t)out_size * sizeof(float));
    qkv_kernel<<<128, 256>>>(x, Wq, Wk, Wv);
    stats_kernel<<<dim3(16, 4, BB), 256, stats_smem>>>();
    pv_kernel<<<dim3(8, 16, BB), 256, pv_smem>>>(out);
}

// round 7
// speedup vs baseline: 5.6310x; 1.0463x over previous
#include <cuda_runtime.h>
#include <math.h>
#include <stdint.h>

#define BB 8
#define TT 2048
#define CC 384
#define HH 64
#define NTOK (BB * TT)   // 16384

__device__ uint32_t g_qkv[3 * NTOK * HH];         // q | k | v, tf32 bits
__device__ float g_Z[NTOK];                       // per-(b,s) column sum of exp

__device__ __forceinline__ uint32_t f2tf(float f) {
    uint32_t r; asm("cvt.rna.tf32.f32 %0, %1;" : "=r"(r) : "f"(f)); return r;
}
__device__ __forceinline__ float frcp(float f) {
    float r; asm("rcp.approx.f32 %0, %1;" : "=f"(r) : "f"(f)); return r;
}
__device__ __forceinline__ void mma8(float* c, const uint32_t* a, const uint32_t* b) {
    asm volatile(
        "mma.sync.aligned.m16n8k8.row.col.f32.tf32.tf32.f32 "
        "{%0,%1,%2,%3}, {%4,%5,%6,%7}, {%8,%9}, {%0,%1,%2,%3};\n"
        : "+f"(c[0]), "+f"(c[1]), "+f"(c[2]), "+f"(c[3])
        : "r"(a[0]), "r"(a[1]), "r"(a[2]), "r"(a[3]), "r"(b[0]), "r"(b[1]));
}
__device__ __forceinline__ void cpa16(uint32_t s, const void* g) {
    asm volatile("cp.async.cg.shared.global [%0], [%1], 16;" :: "r"(s), "l"(g));
}
__device__ __forceinline__ void cp_commit() { asm volatile("cp.async.commit_group;"); }
template<int N> __device__ __forceinline__ void cp_wait() {
    asm volatile("cp.async.wait_group %0;" :: "n"(N));
}

// ---------------------------------------------------------------------------
// Kernel A: fused QKV projection. grid(128), 512 thr (16 warps).
// Warp layout 4(m) x 4(n): warp tile 32x16 per output matrix. Zeroes g_Z.
// ---------------------------------------------------------------------------
__global__ void __launch_bounds__(512, 1) qkv_kernel(
        const float* __restrict__ x,
        const float* __restrict__ Wq,
        const float* __restrict__ Wk,
        const float* __restrict__ Wv) {
    __shared__ float Xs[2][128][36];      // pad 36 (==4 mod 32)
    __shared__ float Ws[2][3][32][72];    // pad 72 (==8 mod 32)
    const uint32_t XB = (uint32_t)__cvta_generic_to_shared(&Xs[0][0][0]);
    const uint32_t WB = (uint32_t)__cvta_generic_to_shared(&Ws[0][0][0][0]);
    const float* Wmat[3] = {Wq, Wk, Wv};

    const int r0  = blockIdx.x * 128;
    const int tid = threadIdx.x, lane = tid & 31, wid = tid >> 5;
    const int lr = lane >> 2, lc = lane & 3;
    const int wm = (wid >> 2) * 32, wn = (wid & 3) * 16;

    if (tid < 128) g_Z[blockIdx.x * 128 + tid] = 0.f;

    for (int i = tid; i < 1024; i += 512) {
        int r = i >> 3, c4 = i & 7;
        cpa16(XB + (r * 36 + c4 * 4) * 4, x + (size_t)(r0 + r) * CC + c4 * 4);
    }
    for (int i = tid; i < 1536; i += 512) {
        int w = i >> 9, j = i & 511, r = j >> 4, c4 = j & 15;
        cpa16(WB + ((w * 32 + r) * 72 + c4 * 4) * 4, Wmat[w] + (size_t)r * HH + c4 * 4);
    }
    cp_commit();

    float acc[3][2][2][4] = {};
    for (int k0 = 0; k0 < CC; k0 += 32) {
        const int st = (k0 >> 5) & 1;
        if (k0 + 32 < CC) {
            const uint32_t xD = XB + (st ^ 1) * 128 * 36 * 4;
            const uint32_t wD = WB + (st ^ 1) * 3 * 32 * 72 * 4;
            for (int i = tid; i < 1024; i += 512) {
                int r = i >> 3, c4 = i & 7;
                cpa16(xD + (r * 36 + c4 * 4) * 4,
                      x + (size_t)(r0 + r) * CC + k0 + 32 + c4 * 4);
            }
            for (int i = tid; i < 1536; i += 512) {
                int w = i >> 9, j = i & 511, r = j >> 4, c4 = j & 15;
                cpa16(wD + ((w * 32 + r) * 72 + c4 * 4) * 4,
                      Wmat[w] + (size_t)(k0 + 32 + r) * HH + c4 * 4);
            }
            cp_commit();
            cp_wait<1>();
        } else {
            cp_wait<0>();
        }
        __syncthreads();

        #pragma unroll
        for (int ks = 0; ks < 4; ks++) {
            const int k = ks * 8;
            uint32_t a[2][4];
            #pragma unroll
            for (int mi = 0; mi < 2; mi++) {
                int rb = wm + mi * 16;
                a[mi][0] = f2tf(Xs[st][rb + lr][k + lc]);
                a[mi][1] = f2tf(Xs[st][rb + lr + 8][k + lc]);
                a[mi][2] = f2tf(Xs[st][rb + lr][k + lc + 4]);
                a[mi][3] = f2tf(Xs[st][rb + lr + 8][k + lc + 4]);
            }
            #pragma unroll
            for (int w = 0; w < 3; w++) {
                uint32_t bf[2][2];
                #pragma unroll
                for (int ni = 0; ni < 2; ni++) {
                    int cb = wn + ni * 8 + lr;
                    bf[ni][0] = f2tf(Ws[st][w][k + lc][cb]);
                    bf[ni][1] = f2tf(Ws[st][w][k + lc + 4][cb]);
                }
                #pragma unroll
                for (int mi = 0; mi < 2; mi++)
                    #pragma unroll
                    for (int ni = 0; ni < 2; ni++)
                        mma8(acc[w][mi][ni], a[mi], bf[ni]);
            }
        }
        __syncthreads();
    }

    #pragma unroll
    for (int w = 0; w < 3; w++) {
        uint32_t* dst = &g_qkv[(size_t)w * NTOK * HH];
        #pragma unroll
        for (int mi = 0; mi < 2; mi++)
            #pragma unroll
            for (int ni = 0; ni < 2; ni++) {
                int row = r0 + wm + mi * 16 + lr;
                int col = wn + ni * 8 + 2 * lc;
                *(uint2*)&dst[(size_t)row * HH + col] =
                    make_uint2(f2tf(acc[w][mi][ni][0]), f2tf(acc[w][mi][ni][1]));
                *(uint2*)&dst[(size_t)(row + 8) * HH + col] =
                    make_uint2(f2tf(acc[w][mi][ni][2]), f2tf(acc[w][mi][ni][3]));
            }
    }
}

// ---------------------------------------------------------------------------
// Kernel B: Z[s] = sum_{t>=s} exp(scale*q_t.k_s). cp.async double-buffered Q.
// grid(16 s-tiles, 4 t-chunks, B), 256 thr, K tile persistent.
// ---------------------------------------------------------------------------
__global__ void __launch_bounds__(256, 2) stats_kernel() {
    extern __shared__ uint32_t sm_[];
    uint32_t (*Ks)[68]      = (uint32_t(*)[68])sm_;
    uint32_t (*Qs)[128][68] = (uint32_t(*)[128][68])(sm_ + 128 * 68);
    const uint32_t sbase = (uint32_t)__cvta_generic_to_shared(sm_);
    const uint32_t KS_B = sbase, QS_B = sbase + 128 * 68 * 4;

    const int si = blockIdx.x, c = blockIdx.y, b = blockIdx.z;
    const int tBeg = max(si, c * 4), tEnd = min(16, c * 4 + 4);
    if (tBeg >= tEnd) return;
    const int s0 = si * 128;
    const uint32_t* q  = &g_qkv[(size_t)b * TT * HH];
    const uint32_t* kp = &g_qkv[(size_t)(NTOK + b * TT) * HH];
    const int tid = threadIdx.x, lane = tid & 31, wid = tid >> 5;
    const int lr = lane >> 2, lc = lane & 3;
    const int wm = (wid >> 2) * 64, wn = (wid & 3) * 32;
    const float scale = rsqrtf((float)CC);

    for (int i = tid; i < 2048; i += 256) {
        int r = i >> 4, c4 = i & 15;
        cpa16(KS_B + (r * 68 + c4 * 4) * 4, kp + (size_t)(s0 + r) * HH + c4 * 4);
        cpa16(QS_B + (r * 68 + c4 * 4) * 4, q + (size_t)(tBeg * 128 + r) * HH + c4 * 4);
    }
    cp_commit();

    float colsum[4][2] = {};
    for (int ti = tBeg; ti < tEnd; ti++) {
        const int st = (ti - tBeg) & 1;
        if (ti + 1 < tEnd) {
            const uint32_t dstB = QS_B + (st ^ 1) * 128 * 68 * 4;
            for (int i = tid; i < 2048; i += 256) {
                int r = i >> 4, c4 = i & 15;
                cpa16(dstB + (r * 68 + c4 * 4) * 4,
                      q + (size_t)((ti + 1) * 128 + r) * HH + c4 * 4);
            }
            cp_commit();
            cp_wait<1>();
        } else {
            cp_wait<0>();
        }
        __syncthreads();

        const int t0 = ti * 128;
        float acc[4][4][4] = {};
        #pragma unroll
        for (int ks = 0; ks < 8; ks++) {
            const int k = ks * 8;
            uint32_t a[4][4], bf[4][2];
            #pragma unroll
            for (int mi = 0; mi < 4; mi++) {
                int rb = wm + mi * 16;
                a[mi][0] = Qs[st][rb + lr][k + lc];
                a[mi][1] = Qs[st][rb + lr + 8][k + lc];
                a[mi][2] = Qs[st][rb + lr][k + lc + 4];
                a[mi][3] = Qs[st][rb + lr + 8][k + lc + 4];
            }
            #pragma unroll
            for (int ni = 0; ni < 4; ni++) {
                int sb = wn + ni * 8 + lr;
                bf[ni][0] = Ks[sb][k + lc];
                bf[ni][1] = Ks[sb][k + lc + 4];
            }
            #pragma unroll
            for (int mi = 0; mi < 4; mi++)
                #pragma unroll
                for (int ni = 0; ni < 4; ni++)
                    mma8(acc[mi][ni], a[mi], bf[ni]);
        }

        #pragma unroll
        for (int mi = 0; mi < 4; mi++)
            #pragma unroll
            for (int ni = 0; ni < 4; ni++) {
                int tg = t0 + wm + mi * 16 + lr;
                int sg = s0 + wn + ni * 8 + 2 * lc;
                float e0 = (tg >= sg)         ? __expf(acc[mi][ni][0] * scale) : 0.f;
                float e1 = (tg >= sg + 1)     ? __expf(acc[mi][ni][1] * scale) : 0.f;
                float e2 = (tg + 8 >= sg)     ? __expf(acc[mi][ni][2] * scale) : 0.f;
                float e3 = (tg + 8 >= sg + 1) ? __expf(acc[mi][ni][3] * scale) : 0.f;
                colsum[ni][0] += e0 + e2;
                colsum[ni][1] += e1 + e3;
            }
        __syncthreads();
    }

    #pragma unroll
    for (int ni = 0; ni < 4; ni++)
        #pragma unroll
        for (int jj = 0; jj < 2; jj++) {
            float v = colsum[ni][jj];
            v += __shfl_xor_sync(0xffffffffu, v, 16);
            v += __shfl_xor_sync(0xffffffffu, v, 8);
            v += __shfl_xor_sync(0xffffffffu, v, 4);
            colsum[ni][jj] = v;
        }
    if (lr == 0) {
        #pragma unroll
        for (int ni = 0; ni < 4; ni++) {
            int sg = s0 + wn + ni * 8 + 2 * lc;
            atomicAdd(&g_Z[b * TT + sg],     colsum[ni][0]);
            atomicAdd(&g_Z[b * TT + sg + 1], colsum[ni][1]);
        }
    }
}

// ---------------------------------------------------------------------------
// Kernel D: fused recompute QK^T -> P -> PV. Single-buffered K/V (2 CTAs/SM),
// K[s+1] prefetched during PV phase, V[s+1]/Z[s+1] during next QK.
// grid(8 s-chunks of 4x64, 16 t-tiles, B), 256 thr.
// smem words: Qs 0..8704, Ps ..17408, Ks ..21760, Vs ..26368, Zs ..26432,
// rZs ..26496  => 26496*4 = 105984 bytes.
// ---------------------------------------------------------------------------
__global__ void __launch_bounds__(256, 2) pv_kernel(float* __restrict__ out) {
    extern __shared__ uint32_t sm_[];
    uint32_t (*Qs)[68] = (uint32_t(*)[68])sm_;                 // 128x64
    uint32_t (*Ps)[68] = (uint32_t(*)[68])(sm_ + 8704);        // 128x64
    uint32_t (*Ks)[68] = (uint32_t(*)[68])(sm_ + 17408);       // 64x64
    uint32_t (*Vs)[72] = (uint32_t(*)[72])(sm_ + 21760);       // 64x64
    float*    Zs       = (float*)(sm_ + 26368);
    float*    rZs      = (float*)(sm_ + 26432);
    const uint32_t sbase = (uint32_t)__cvta_generic_to_shared(sm_);
    const uint32_t QS_B = sbase, KS_B = sbase + 17408 * 4,
                   VS_B = sbase + 21760 * 4, ZS_B = sbase + 26368 * 4;

    const int c = blockIdx.x, ti = blockIdx.y, b = blockIdx.z;
    const int sBeg = c * 4;
    const int sEnd = min(sBeg + 4, 2 * (ti + 1));
    if (sBeg >= sEnd) return;
    const int t0 = ti * 128;

    const uint32_t* q  = &g_qkv[(size_t)b * TT * HH];
    const uint32_t* kp = &g_qkv[(size_t)(NTOK + b * TT) * HH];
    const uint32_t* vp = &g_qkv[(size_t)(2 * NTOK + b * TT) * HH];
    const float* Zg = &g_Z[b * TT];
    const int tid = threadIdx.x, lane = tid & 31, wid = tid >> 5;
    const int lr = lane >> 2, lc = lane & 3;
    const float scale = rsqrtf((float)CC);
    const int wmq = (wid >> 2) * 64, wnq = (wid & 3) * 16;
    const int wm  = (wid >> 1) * 32, wn  = (wid & 1) * 32;

    // prologue: Q + K0 + V0 + Z0, one group
    for (int i = tid; i < 2048; i += 256) {
        int r = i >> 4, c4 = i & 15;
        cpa16(QS_B + (r * 68 + c4 * 4) * 4, q + (size_t)(t0 + r) * HH + c4 * 4);
    }
    {
        const int s0 = sBeg * 64;
        for (int i = tid; i < 1024; i += 256) {
            int r = i >> 4, c4 = i & 15;
            cpa16(KS_B + (r * 68 + c4 * 4) * 4, kp + (size_t)(s0 + r) * HH + c4 * 4);
            cpa16(VS_B + (r * 72 + c4 * 4) * 4, vp + (size_t)(s0 + r) * HH + c4 * 4);
        }
        if (tid < 16) cpa16(ZS_B + tid * 16, Zg + s0 + tid * 4);
    }
    cp_commit();

    float acc_o[2][4][4] = {};

    for (int s64 = sBeg; s64 < sEnd; s64++) {
        cp_wait<0>();
        if (tid < 16) {
            #pragma unroll
            for (int j = 0; j < 4; j++)
                rZs[tid * 4 + j] = frcp(Zs[tid * 4 + j]);
        }
        __syncthreads();

        const int s0 = s64 * 64;
        // --- QK^T: 128x64x64 ---
        float acc_qk[4][2][4] = {};
        #pragma unroll
        for (int ks = 0; ks < 8; ks++) {
            const int k = ks * 8;
            uint32_t a[4][4], bf[2][2];
            #pragma unroll
            for (int mi = 0; mi < 4; mi++) {
                int rb = wmq + mi * 16;
                a[mi][0] = Qs[rb + lr][k + lc];
                a[mi][1] = Qs[rb + lr + 8][k + lc];
                a[mi][2] = Qs[rb + lr][k + lc + 4];
                a[mi][3] = Qs[rb + lr + 8][k + lc + 4];
            }
            #pragma unroll
            for (int ni = 0; ni < 2; ni++) {
                int sb = wnq + ni * 8 + lr;
                bf[ni][0] = Ks[sb][k + lc];
                bf[ni][1] = Ks[sb][k + lc + 4];
            }
            #pragma unroll
            for (int mi = 0; mi < 4; mi++)
                #pragma unroll
                for (int ni = 0; ni < 2; ni++)
                    mma8(acc_qk[mi][ni], a[mi], bf[ni]);
        }

        // --- P = exp(S)*rZ -> smem ---
        #pragma unroll
        for (int mi = 0; mi < 4; mi++)
            #pragma unroll
            for (int ni = 0; ni < 2; ni++) {
                int tr = wmq + mi * 16 + lr;
                int sc = wnq + ni * 8 + 2 * lc;
                int tg = t0 + tr, sg = s0 + sc;
                float z0 = rZs[sc], z1 = rZs[sc + 1];
                uint2 u;
                u.x = f2tf((tg >= sg)     ? __expf(acc_qk[mi][ni][0] * scale) * z0 : 0.f);
                u.y = f2tf((tg >= sg + 1) ? __expf(acc_qk[mi][ni][1] * scale) * z1 : 0.f);
                *(uint2*)&Ps[tr][sc] = u;
                u.x = f2tf((tg + 8 >= sg)     ? __expf(acc_qk[mi][ni][2] * scale) * z0 : 0.f);
                u.y = f2tf((tg + 8 >= sg + 1) ? __expf(acc_qk[mi][ni][3] * scale) * z1 : 0.f);
                *(uint2*)&Ps[tr + 8][sc] = u;
            }
        __syncthreads();   // K consumed, Ps visible

        // prefetch K[s+1] -> overlaps PV phase
        if (s64 + 1 < sEnd) {
            const int s0n = (s64 + 1) * 64;
            for (int i = tid; i < 1024; i += 256) {
                int r = i >> 4, c4 = i & 15;
                cpa16(KS_B + (r * 68 + c4 * 4) * 4, kp + (size_t)(s0n + r) * HH + c4 * 4);
            }
            cp_commit();
        }

        // --- O += P(128x64) @ V(64x64) ---
        #pragma unroll
        for (int ks = 0; ks < 8; ks++) {
            const int k = ks * 8;
            uint32_t a[2][4], bf[4][2];
            #pragma unroll
            for (int mi = 0; mi < 2; mi++) {
                int rb = wm + mi * 16;
                a[mi][0] = Ps[rb + lr][k + lc];
                a[mi][1] = Ps[rb + lr + 8][k + lc];
                a[mi][2] = Ps[rb + lr][k + lc + 4];
                a[mi][3] = Ps[rb + lr + 8][k + lc + 4];
            }
            #pragma unroll
            for (int ni = 0; ni < 4; ni++) {
                int cb = wn + ni * 8 + lr;
                bf[ni][0] = Vs[k + lc][cb];
                bf[ni][1] = Vs[k + lc + 4][cb];
            }
            #pragma unroll
            for (int mi = 0; mi < 2; mi++)
                #pragma unroll
                for (int ni = 0; ni < 4; ni++)
                    mma8(acc_o[mi][ni], a[mi], bf[ni]);
        }
        __syncthreads();   // V consumed

        // prefetch V[s+1], Z[s+1]
        if (s64 + 1 < sEnd) {
            const int s0n = (s64 + 1) * 64;
            for (int i = tid; i < 1024; i += 256) {
                int r = i >> 4, c4 = i & 15;
                cpa16(VS_B + (r * 72 + c4 * 4) * 4, vp + (size_t)(s0n + r) * HH + c4 * 4);
            }
            if (tid < 16) cpa16(ZS_B + tid * 16, Zg + s0n + tid * 4);
            cp_commit();
        }
    }

    #pragma unroll
    for (int mi = 0; mi < 2; mi++)
        #pragma unroll
        for (int ni = 0; ni < 4; ni++) {
            int row = b * TT + t0 + wm + mi * 16 + lr;
            int col = wn + ni * 8 + 2 * lc;
            float* o = &out[(size_t)row * HH + col];
            atomicAdd(o,     acc_o[mi][ni][0]);
            atomicAdd(o + 1, acc_o[mi][ni][1]);
            float* o2 = o + 8 * HH;
            atomicAdd(o2,     acc_o[mi][ni][2]);
            atomicAdd(o2 + 1, acc_o[mi][ni][3]);
        }
}

// ---------------------------------------------------------------------------
extern "C" void kernel_launch(void* const* d_in, const int* in_sizes, int n_in,
                              void* d_out, int out_size) {
    const float* x  = (const float*)d_in[0];
    const float* Wq = (const float*)d_in[1];
    const float* Wk = (const float*)d_in[2];
    const float* Wv = (const float*)d_in[3];
    float* out = (float*)d_out;

    const int stats_smem = (128 * 68 + 2 * 128 * 68) * 4;   // 104448
    const int pv_smem    = 26496 * 4;                       // 105984  (FIXED)
    cudaFuncSetAttribute(stats_kernel, cudaFuncAttributeMaxDynamicSharedMemorySize, stats_smem);
    cudaFuncSetAttribute(pv_kernel,    cudaFuncAttributeMaxDynamicSharedMemorySize, pv_smem);

    cudaMemsetAsync(d_out, 0, (size_t)out_size * sizeof(float));
    qkv_kernel<<<128, 512>>>(x, Wq, Wk, Wv);
    stats_kernel<<<dim3(16, 4, BB), 256, stats_smem>>>();
    pv_kernel<<<dim3(8, 16, BB), 256, pv_smem>>>(out);
}